// round 1
// baseline (speedup 1.0000x reference)
#include <cuda_runtime.h>
#include <cstddef>

// ---------------- problem constants ----------------
constexpr int kB = 8;
constexpr int kS = 512;          // src len == tgt len
constexpr int kD = 512;          // d_model
constexpr int kH = 8;            // heads
constexpr int kDK = 64;          // head dim
constexpr int kL = 6;            // layers
constexpr int kF = 2048;         // ffn dim
constexpr int kV = 32000;        // vocab
constexpr int kNT = kB * kS;     // 4096 tokens per side
constexpr float kNEG = -1e9f;
constexpr float kEPS = 1e-5f;
constexpr float kSCALE = 0.125f; // 1/sqrt(64)

// ---------------- device scratch (no allocations allowed) ----------------
__device__ float g_x[kNT * kD];     // encoder activations / enc_out
__device__ float g_y[kNT * kD];     // decoder activations
__device__ float g_q[kNT * kD];
__device__ float g_k[kNT * kD];
__device__ float g_v[kNT * kD];
__device__ float g_t[kNT * kD];     // sublayer output (attn proj / ffn2)
__device__ float g_ffn[kNT * kF];
__device__ float g_sc[(size_t)kB * kH * kS * kS];   // 64 MB scores

// ---------------- embedding + positional encoding ----------------
__global__ void embed_kernel(const int* __restrict__ tok,
                             const float* __restrict__ emb,
                             const float* __restrict__ pos,
                             float* __restrict__ out) {
    int i = blockIdx.x * blockDim.x + threadIdx.x;   // over kNT*kD
    int d = i & (kD - 1);
    int t = i >> 9;           // / kD
    int s = t & (kS - 1);
    out[i] = emb[(size_t)tok[t] * kD + d] + pos[s * kD + d];
}

// ---------------- generic SGEMM: C = A[MxK] * B[KxN] + bias (+ReLU) ----------
// BM=BN=128, BK=8, 256 threads, 8x8 per thread. M%128==0, N%128==0, K%8==0.
template <bool RELU>
__global__ __launch_bounds__(256)
void sgemm_kernel(const float* __restrict__ A, const float* __restrict__ B,
                  const float* __restrict__ bias, float* __restrict__ C,
                  int M, int N, int K) {
    __shared__ float As[8][128];
    __shared__ float Bs[8][128];

    const int tid = threadIdx.x;
    const int tx = tid & 15, ty = tid >> 4;
    const int bm = blockIdx.y << 7, bn = blockIdx.x << 7;

    const int arow = tid >> 1;
    const int acol = (tid & 1) << 2;
    const int brow = tid >> 5;
    const int bcol = (tid & 31) << 2;

    const float* Ap = A + (size_t)(bm + arow) * K + acol;
    const float* Bp = B + (size_t)brow * N + bn + bcol;

    float acc[8][8] = {};

    float4 a0 = *(const float4*)Ap;
    float4 b0 = *(const float4*)Bp;

    for (int k0 = 0;;) {
        As[acol + 0][arow] = a0.x;
        As[acol + 1][arow] = a0.y;
        As[acol + 2][arow] = a0.z;
        As[acol + 3][arow] = a0.w;
        *(float4*)&Bs[brow][bcol] = b0;
        __syncthreads();

        k0 += 8;
        const bool more = (k0 < K);
        if (more) {
            a0 = *(const float4*)(Ap + k0);
            b0 = *(const float4*)(Bp + (size_t)k0 * N);
        }

#pragma unroll
        for (int kk = 0; kk < 8; kk++) {
            float4 ra0 = *(const float4*)&As[kk][ty << 3];
            float4 ra1 = *(const float4*)&As[kk][(ty << 3) + 4];
            float4 rb0 = *(const float4*)&Bs[kk][tx << 3];
            float4 rb1 = *(const float4*)&Bs[kk][(tx << 3) + 4];
            float ra[8] = {ra0.x, ra0.y, ra0.z, ra0.w, ra1.x, ra1.y, ra1.z, ra1.w};
            float rb[8] = {rb0.x, rb0.y, rb0.z, rb0.w, rb1.x, rb1.y, rb1.z, rb1.w};
#pragma unroll
            for (int i = 0; i < 8; i++)
#pragma unroll
                for (int j = 0; j < 8; j++)
                    acc[i][j] = fmaf(ra[i], rb[j], acc[i][j]);
        }
        if (!more) break;
        __syncthreads();
    }

    float bb[8];
#pragma unroll
    for (int j = 0; j < 8; j++)
        bb[j] = bias ? bias[bn + (tx << 3) + j] : 0.0f;

#pragma unroll
    for (int i = 0; i < 8; i++) {
        float out[8];
#pragma unroll
        for (int j = 0; j < 8; j++) {
            float vv = acc[i][j] + bb[j];
            if (RELU) vv = fmaxf(vv, 0.0f);
            out[j] = vv;
        }
        float* Cp = C + (size_t)(bm + (ty << 3) + i) * N + bn + (tx << 3);
        *(float4*)Cp = *(float4*)out;
        *(float4*)(Cp + 4) = *(float4*)(out + 4);
    }
}

// ---------------- attention scores: S[bh,q,k] = (Q[q,:h]·K[k,:h]) * scale -----
// grid (kS/64, kS/64, kB*kH), 256 threads, 64x64 tile, full DK=64 in smem.
__global__ __launch_bounds__(256)
void attn_scores_kernel(const float* __restrict__ Q, const float* __restrict__ Kmat,
                        float* __restrict__ Sc) {
    const int bh = blockIdx.z;
    const int b = bh >> 3, h = bh & 7;
    const int q0 = blockIdx.y << 6, k0 = blockIdx.x << 6;

    __shared__ float Qs[64][64];   // [dk][q]
    __shared__ float Ks[64][64];   // [dk][k]

    const int tid = threadIdx.x;
    const float* Qb = Q + (size_t)(b * kS + q0) * kD + h * kDK;
    const float* Kb = Kmat + (size_t)(b * kS + k0) * kD + h * kDK;

#pragma unroll
    for (int it = 0; it < 4; it++) {
        int idx = tid + (it << 8);
        int row = idx >> 4;
        int c4 = (idx & 15) << 2;
        float4 qv = *(const float4*)(Qb + (size_t)row * kD + c4);
        Qs[c4 + 0][row] = qv.x; Qs[c4 + 1][row] = qv.y;
        Qs[c4 + 2][row] = qv.z; Qs[c4 + 3][row] = qv.w;
        float4 kv = *(const float4*)(Kb + (size_t)row * kD + c4);
        Ks[c4 + 0][row] = kv.x; Ks[c4 + 1][row] = kv.y;
        Ks[c4 + 2][row] = kv.z; Ks[c4 + 3][row] = kv.w;
    }
    __syncthreads();

    const int tx = tid & 15, ty = tid >> 4;
    float acc[4][4] = {};
#pragma unroll
    for (int kk = 0; kk < 64; kk++) {
        float4 a4 = *(const float4*)&Qs[kk][ty << 2];
        float4 b4 = *(const float4*)&Ks[kk][tx << 2];
        float ra[4] = {a4.x, a4.y, a4.z, a4.w};
        float rb[4] = {b4.x, b4.y, b4.z, b4.w};
#pragma unroll
        for (int i = 0; i < 4; i++)
#pragma unroll
            for (int j = 0; j < 4; j++)
                acc[i][j] = fmaf(ra[i], rb[j], acc[i][j]);
    }

#pragma unroll
    for (int i = 0; i < 4; i++) {
        float out[4] = {acc[i][0] * kSCALE, acc[i][1] * kSCALE,
                        acc[i][2] * kSCALE, acc[i][3] * kSCALE};
        float* Sp = Sc + ((size_t)bh * kS + q0 + (ty << 2) + i) * kS + k0 + (tx << 2);
        *(float4*)Sp = *(float4*)out;
    }
}

// ---------------- masked softmax (in place, one block per row) --------------
// mode 0: key mask   -> valid(k) = ktok[b*kS+k] != 0
// mode 1: dec self   -> valid(k) = (qtok[b*kS+q] != 0) && (k <= q)
__global__ __launch_bounds__(128)
void softmax_kernel(float* __restrict__ Sc, const int* __restrict__ qtok,
                    const int* __restrict__ ktok, int mode) {
    const int r = blockIdx.x;             // [0, kB*kH*kS)
    const int q = r & (kS - 1);
    const int bh = r >> 9;
    const int b = bh >> 3;
    float* row = Sc + (size_t)r * kS;
    const int tid = threadIdx.x;

    bool qvalid = true;
    if (mode == 1) qvalid = (qtok[b * kS + q] != 0);

    float v[4];
#pragma unroll
    for (int i = 0; i < 4; i++) {
        int k = tid + (i << 7);
        float s = row[k];
        bool valid = (mode == 0) ? (ktok[b * kS + k] != 0) : (qvalid && (k <= q));
        v[i] = valid ? s : kNEG;
    }

    __shared__ float red[4];
    float m = fmaxf(fmaxf(v[0], v[1]), fmaxf(v[2], v[3]));
    for (int o = 16; o; o >>= 1) m = fmaxf(m, __shfl_xor_sync(0xffffffffu, m, o));
    if ((tid & 31) == 0) red[tid >> 5] = m;
    __syncthreads();
    m = fmaxf(fmaxf(red[0], red[1]), fmaxf(red[2], red[3]));
    __syncthreads();

    float sum = 0.0f;
#pragma unroll
    for (int i = 0; i < 4; i++) { v[i] = expf(v[i] - m); sum += v[i]; }
    for (int o = 16; o; o >>= 1) sum += __shfl_xor_sync(0xffffffffu, sum, o);
    if ((tid & 31) == 0) red[tid >> 5] = sum;
    __syncthreads();
    sum = red[0] + red[1] + red[2] + red[3];

    float inv = 1.0f / sum;
#pragma unroll
    for (int i = 0; i < 4; i++) row[tid + (i << 7)] = v[i] * inv;
}

// ---------------- PV: O[q, h*64+d] = sum_k P[q,k] * V[k, h*64+d] -------------
// grid (kS/64, kB*kH), 256 threads, 64(q) x 64(d) tile, K chunks of 16.
__global__ __launch_bounds__(256)
void attn_pv_kernel(const float* __restrict__ P, const float* __restrict__ V,
                    float* __restrict__ O) {
    const int bh = blockIdx.y;
    const int b = bh >> 3, h = bh & 7;
    const int q0 = blockIdx.x << 6;

    __shared__ float Ps[16][64];   // [k][q]
    __shared__ float Vs[16][64];   // [k][d]

    const int tid = threadIdx.x;
    const int tx = tid & 15, ty = tid >> 4;
    const float* Pb = P + (size_t)bh * kS * kS + (size_t)q0 * kS;
    const float* Vb = V + (size_t)b * kS * kD + h * kDK;

    const int pq = tid >> 2, pc = (tid & 3) << 2;
    const int vk = tid >> 4, vc = (tid & 15) << 2;

    float acc[4][4] = {};
    for (int k0 = 0; k0 < kS; k0 += 16) {
        float4 pv = *(const float4*)(Pb + (size_t)pq * kS + k0 + pc);
        Ps[pc + 0][pq] = pv.x; Ps[pc + 1][pq] = pv.y;
        Ps[pc + 2][pq] = pv.z; Ps[pc + 3][pq] = pv.w;
        *(float4*)&Vs[vk][vc] = *(const float4*)(Vb + (size_t)(k0 + vk) * kD + vc);
        __syncthreads();
#pragma unroll
        for (int kk = 0; kk < 16; kk++) {
            float4 a4 = *(const float4*)&Ps[kk][ty << 2];
            float4 b4 = *(const float4*)&Vs[kk][tx << 2];
            float ra[4] = {a4.x, a4.y, a4.z, a4.w};
            float rb[4] = {b4.x, b4.y, b4.z, b4.w};
#pragma unroll
            for (int i = 0; i < 4; i++)
#pragma unroll
                for (int j = 0; j < 4; j++)
                    acc[i][j] = fmaf(ra[i], rb[j], acc[i][j]);
        }
        __syncthreads();
    }

#pragma unroll
    for (int i = 0; i < 4; i++) {
        float out[4] = {acc[i][0], acc[i][1], acc[i][2], acc[i][3]};
        float* Op = O + (size_t)(b * kS + q0 + (ty << 2) + i) * kD + h * kDK + (tx << 2);
        *(float4*)Op = *(float4*)out;
    }
}

// ---------------- x = LayerNorm(x + a) * g + b ------------------------------
__global__ __launch_bounds__(128)
void add_ln_kernel(float* __restrict__ x, const float* __restrict__ a,
                   const float* __restrict__ g, const float* __restrict__ bet) {
    const int r = blockIdx.x;
    const int tid = threadIdx.x;
    __shared__ float red[4];

    float v[4];
#pragma unroll
    for (int i = 0; i < 4; i++) {
        int c = tid + (i << 7);
        size_t idx = (size_t)r * kD + c;
        v[i] = x[idx] + a[idx];
    }

    float s = v[0] + v[1] + v[2] + v[3];
    for (int o = 16; o; o >>= 1) s += __shfl_xor_sync(0xffffffffu, s, o);
    if ((tid & 31) == 0) red[tid >> 5] = s;
    __syncthreads();
    s = red[0] + red[1] + red[2] + red[3];
    __syncthreads();
    const float mu = s * (1.0f / kD);

    float sq = 0.0f;
#pragma unroll
    for (int i = 0; i < 4; i++) { float d = v[i] - mu; sq += d * d; }
    for (int o = 16; o; o >>= 1) sq += __shfl_xor_sync(0xffffffffu, sq, o);
    if ((tid & 31) == 0) red[tid >> 5] = sq;
    __syncthreads();
    sq = red[0] + red[1] + red[2] + red[3];
    const float rstd = rsqrtf(sq * (1.0f / kD) + kEPS);

#pragma unroll
    for (int i = 0; i < 4; i++) {
        int c = tid + (i << 7);
        x[(size_t)r * kD + c] = (v[i] - mu) * rstd * g[c] + bet[c];
    }
}

// ---------------- host-side orchestration ----------------------------------
static void gemm(const float* A, const float* B, const float* bias, float* C,
                 int M, int N, int K, bool relu) {
    dim3 grid(N / 128, M / 128);
    if (relu) sgemm_kernel<true><<<grid, 256>>>(A, B, bias, C, M, N, K);
    else      sgemm_kernel<false><<<grid, 256>>>(A, B, bias, C, M, N, K);
}

// One full MHA sublayer: out <- Proj(Attn(qin, kvin)).
// W: 4 contiguous [kD,kD] matrices (q,k,v,out); bias: 4 x [kD].
static void attention(const float* qin, const float* kvin,
                      const float* W, const float* bias,
                      float* out, const int* qtok, const int* ktok, int mode,
                      float* bq, float* bk, float* bv, float* bsc) {
    const size_t DD = (size_t)kD * kD;
    gemm(qin,  W + 0 * DD, bias + 0 * kD, bq, kNT, kD, kD, false);
    gemm(kvin, W + 1 * DD, bias + 1 * kD, bk, kNT, kD, kD, false);
    gemm(kvin, W + 2 * DD, bias + 2 * kD, bv, kNT, kD, kD, false);
    attn_scores_kernel<<<dim3(kS / 64, kS / 64, kB * kH), 256>>>(bq, bk, bsc);
    softmax_kernel<<<kB * kH * kS, 128>>>(bsc, qtok, ktok, mode);
    attn_pv_kernel<<<dim3(kS / 64, kB * kH), 256>>>(bsc, bv, bq);  // reuse bq as ctx
    gemm(bq, W + 3 * DD, bias + 3 * kD, out, kNT, kD, kD, false);
}

extern "C" void kernel_launch(void* const* d_in, const int* in_sizes, int n_in,
                              void* d_out, int out_size) {
    const int*   src       = (const int*)d_in[0];
    const int*   tgt       = (const int*)d_in[1];
    const float* enc_emb   = (const float*)d_in[2];
    const float* dec_emb   = (const float*)d_in[3];
    const float* pos       = (const float*)d_in[4];
    const float* enc_aw    = (const float*)d_in[5];
    const float* enc_ab    = (const float*)d_in[6];
    const float* enc_w1    = (const float*)d_in[7];
    const float* enc_b1    = (const float*)d_in[8];
    const float* enc_w2    = (const float*)d_in[9];
    const float* enc_b2    = (const float*)d_in[10];
    const float* enc_lng   = (const float*)d_in[11];
    const float* enc_lnb   = (const float*)d_in[12];
    const float* dec_aw    = (const float*)d_in[13];
    const float* dec_ab    = (const float*)d_in[14];
    const float* dec_w1    = (const float*)d_in[15];
    const float* dec_b1    = (const float*)d_in[16];
    const float* dec_w2    = (const float*)d_in[17];
    const float* dec_b2    = (const float*)d_in[18];
    const float* dec_lng   = (const float*)d_in[19];
    const float* dec_lnb   = (const float*)d_in[20];
    const float* fc_w      = (const float*)d_in[21];
    const float* fc_b      = (const float*)d_in[22];

    float *x, *y, *q, *k, *v, *t, *ffn, *sc;
    cudaGetSymbolAddress((void**)&x,   g_x);
    cudaGetSymbolAddress((void**)&y,   g_y);
    cudaGetSymbolAddress((void**)&q,   g_q);
    cudaGetSymbolAddress((void**)&k,   g_k);
    cudaGetSymbolAddress((void**)&v,   g_v);
    cudaGetSymbolAddress((void**)&t,   g_t);
    cudaGetSymbolAddress((void**)&ffn, g_ffn);
    cudaGetSymbolAddress((void**)&sc,  g_sc);

    const size_t DD = (size_t)kD * kD;
    const int embBlocks = (kNT * kD) / 256;

    // ---------------- encoder ----------------
    embed_kernel<<<embBlocks, 256>>>(src, enc_emb, pos, x);
    for (int l = 0; l < kL; l++) {
        const float* W  = enc_aw + (size_t)l * 4 * DD;
        const float* Wb = enc_ab + (size_t)l * 4 * kD;
        attention(x, x, W, Wb, t, nullptr, src, 0, q, k, v, sc);
        add_ln_kernel<<<kNT, 128>>>(x, t, enc_lng + (size_t)(l * 2 + 0) * kD,
                                    enc_lnb + (size_t)(l * 2 + 0) * kD);
        gemm(x, enc_w1 + (size_t)l * kD * kF, enc_b1 + (size_t)l * kF, ffn, kNT, kF, kD, true);
        gemm(ffn, enc_w2 + (size_t)l * kF * kD, enc_b2 + (size_t)l * kD, t, kNT, kD, kF, false);
        add_ln_kernel<<<kNT, 128>>>(x, t, enc_lng + (size_t)(l * 2 + 1) * kD,
                                    enc_lnb + (size_t)(l * 2 + 1) * kD);
    }
    // x now holds enc_out

    // ---------------- decoder ----------------
    embed_kernel<<<embBlocks, 256>>>(tgt, dec_emb, pos, y);
    for (int l = 0; l < kL; l++) {
        const float* W  = dec_aw + (size_t)l * 8 * DD;
        const float* Wb = dec_ab + (size_t)l * 8 * kD;
        // self-attention (query-validity + causal mask)
        attention(y, y, W, Wb, t, tgt, tgt, 1, q, k, v, sc);
        add_ln_kernel<<<kNT, 128>>>(y, t, dec_lng + (size_t)(l * 3 + 0) * kD,
                                    dec_lnb + (size_t)(l * 3 + 0) * kD);
        // cross-attention (src key mask)
        attention(y, x, W + 4 * DD, Wb + 4 * kD, t, nullptr, src, 0, q, k, v, sc);
        add_ln_kernel<<<kNT, 128>>>(y, t, dec_lng + (size_t)(l * 3 + 1) * kD,
                                    dec_lnb + (size_t)(l * 3 + 1) * kD);
        // FFN
        gemm(y, dec_w1 + (size_t)l * kD * kF, dec_b1 + (size_t)l * kF, ffn, kNT, kF, kD, true);
        gemm(ffn, dec_w2 + (size_t)l * kF * kD, dec_b2 + (size_t)l * kD, t, kNT, kD, kF, false);
        add_ln_kernel<<<kNT, 128>>>(y, t, dec_lng + (size_t)(l * 3 + 2) * kD,
                                    dec_lnb + (size_t)(l * 3 + 2) * kD);
    }

    // ---------------- final projection to vocab ----------------
    gemm(y, fc_w, fc_b, (float*)d_out, kNT, kV, kD, false);
}

// round 3
// speedup vs baseline: 1.8693x; 1.8693x over previous
#include <cuda_runtime.h>
#include <cuda_fp16.h>
#include <cstddef>
#include <cstdint>

// ---------------- problem constants ----------------
constexpr int kB = 8;
constexpr int kS = 512;
constexpr int kD = 512;
constexpr int kH = 8;
constexpr int kDK = 64;
constexpr int kL = 6;
constexpr int kF = 2048;
constexpr int kV = 32000;
constexpr int kNT = kB * kS;     // 4096 tokens
constexpr float kNEG = -1e9f;
constexpr float kEPS = 1e-5f;
constexpr float kSCALE = 0.125f;

// ---------------- fp16 weight scratch layout (transposed to [N,K]) ---------
constexpr size_t DD  = (size_t)kD * kD;
constexpr size_t DF  = (size_t)kD * kF;
constexpr size_t OFF_EA  = 0;                           // 24 x [512,512]
constexpr size_t OFF_DA  = OFF_EA  + 24 * DD;           // 48 x [512,512]
constexpr size_t OFF_EW1 = OFF_DA  + 48 * DD;
constexpr size_t OFF_EW2 = OFF_EW1 + 6 * DF;
constexpr size_t OFF_DW1 = OFF_EW2 + 6 * DF;
constexpr size_t OFF_DW2 = OFF_DW1 + 6 * DF;
constexpr size_t OFF_FC  = OFF_DW2 + 6 * DF;            // [32000,512]
constexpr size_t W_TOTAL = OFF_FC + (size_t)kV * kD;

// ---------------- device scratch (no allocations allowed) ----------------
__device__ float g_x[kNT * kD];
__device__ float g_y[kNT * kD];
__device__ float g_qkv[kNT * 3 * kD];
__device__ float g_ctx[kNT * kD];
__device__ float g_t[kNT * kD];
__device__ float g_ffn[kNT * kF];
__device__ float g_sc[(size_t)kB * kH * kS * kS];
__device__ __half g_whi[W_TOTAL];
__device__ __half g_wlo[W_TOTAL];

// ========================= helpers ==========================================
__device__ __forceinline__ uint32_t smem_u32(const void* p) {
    uint32_t a;
    asm("{ .reg .u64 t; cvta.to.shared.u64 t, %1; cvt.u32.u64 %0, t; }"
        : "=r"(a) : "l"(p));
    return a;
}

__device__ __forceinline__ void ldsm_x4(uint32_t (&r)[4], uint32_t addr) {
    asm volatile("ldmatrix.sync.aligned.m8n8.x4.shared.b16 {%0,%1,%2,%3}, [%4];"
                 : "=r"(r[0]), "=r"(r[1]), "=r"(r[2]), "=r"(r[3]) : "r"(addr));
}

__device__ __forceinline__ void mma16816(float (&c)[4], const uint32_t (&a)[4],
                                         const uint32_t* b) {
    asm volatile(
        "mma.sync.aligned.m16n8k16.row.col.f32.f16.f16.f32 "
        "{%0,%1,%2,%3}, {%4,%5,%6,%7}, {%8,%9}, {%0,%1,%2,%3};"
        : "+f"(c[0]), "+f"(c[1]), "+f"(c[2]), "+f"(c[3])
        : "r"(a[0]), "r"(a[1]), "r"(a[2]), "r"(a[3]), "r"(b[0]), "r"(b[1]));
}

__device__ __forceinline__ uint32_t pk_h2(__half a, __half b) {
    __half2 t = __halves2half2(a, b);
    return *reinterpret_cast<uint32_t*>(&t);
}

// ============== weight transpose + fp16 hi/lo split: W[K,N] -> [N,K] ========
__global__ __launch_bounds__(256)
void wconv_kernel(const float* __restrict__ W, __half* __restrict__ hi,
                  __half* __restrict__ lo, int K, int N) {
    __shared__ float t[32][33];
    const int n0 = blockIdx.x << 5, k0 = blockIdx.y << 5;
    const int tx = threadIdx.x & 31, ty = threadIdx.x >> 5;
#pragma unroll
    for (int j = 0; j < 32; j += 8)
        t[ty + j][tx] = W[(size_t)(k0 + ty + j) * N + n0 + tx];
    __syncthreads();
#pragma unroll
    for (int j = 0; j < 32; j += 8) {
        float v = t[tx][ty + j];
        __half h = __float2half_rn(v);
        __half l = __float2half_rn(v - __half2float(h));
        size_t o = (size_t)(n0 + ty + j) * K + k0 + tx;
        hi[o] = h;
        lo[o] = l;
    }
}

// ======== HMMA GEMM: C[M,N](ldc) = A[M,K](f32) * Bt[N,K](fp16 hi/lo) + bias =
// 128x128 CTA tile, BK=32, 256 thr (2x4 warps, 64x32 warp tile), 3-pass fp16.
constexpr int APAD = 40;                      // halfs per smem row (32 + pad)
constexpr int SA_BYTES = 128 * APAD * 2;      // 10240
constexpr int STAGE_BYTES = 4 * SA_BYTES;     // Ahi Alo Bhi Blo
constexpr int HG_SMEM = 2 * STAGE_BYTES;      // 81920

template <bool RELU>
__global__ __launch_bounds__(256)
void hgemm_kernel(const float* __restrict__ A,
                  const __half* __restrict__ Bhi,
                  const __half* __restrict__ Blo,
                  const float* __restrict__ bias,
                  float* __restrict__ C,
                  int M, int N, int K, int ldc) {
    extern __shared__ char sm[];
    const int tid = threadIdx.x;
    const int lid = tid & 31, wid = tid >> 5;
    const int wm = wid >> 2, wn = wid & 3;          // 2 x 4 warps
    const int bm = blockIdx.y << 7, bn = blockIdx.x << 7;
    const uint32_t smb = smem_u32(sm);

    const float*  Ap  = A   + (size_t)bm * K;
    const __half* Bhp = Bhi + (size_t)bn * K;
    const __half* Blp = Blo + (size_t)bn * K;

    float4 pa[4];
    uint4 pbh[2], pbl[2];

    auto LOAD = [&](int ch) {
#pragma unroll
        for (int it = 0; it < 4; it++) {
            int i = tid + (it << 8);
            int r = i >> 3, c = (i & 7) << 2;
            pa[it] = *(const float4*)(Ap + (size_t)r * K + ch * 32 + c);
        }
#pragma unroll
        for (int it = 0; it < 2; it++) {
            int i = tid + (it << 8);
            int r = i >> 2, c = (i & 3) << 3;
            pbh[it] = *(const uint4*)(Bhp + (size_t)r * K + ch * 32 + c);
            pbl[it] = *(const uint4*)(Blp + (size_t)r * K + ch * 32 + c);
        }
    };

    auto STORE = [&](int s) {
        __half* sa_hi = (__half*)(sm + s * STAGE_BYTES);
        __half* sa_lo = (__half*)(sm + s * STAGE_BYTES + SA_BYTES);
        __half* sb_hi = (__half*)(sm + s * STAGE_BYTES + 2 * SA_BYTES);
        __half* sb_lo = (__half*)(sm + s * STAGE_BYTES + 3 * SA_BYTES);
#pragma unroll
        for (int it = 0; it < 4; it++) {
            int i = tid + (it << 8);
            int r = i >> 3, c = (i & 7) << 2;
            float4 v = pa[it];
            __half hx = __float2half_rn(v.x), hy = __float2half_rn(v.y);
            __half hz = __float2half_rn(v.z), hw = __float2half_rn(v.w);
            __half lx = __float2half_rn(v.x - __half2float(hx));
            __half ly = __float2half_rn(v.y - __half2float(hy));
            __half lz = __float2half_rn(v.z - __half2float(hz));
            __half lw = __float2half_rn(v.w - __half2float(hw));
            *(uint2*)(sa_hi + r * APAD + c) = make_uint2(pk_h2(hx, hy), pk_h2(hz, hw));
            *(uint2*)(sa_lo + r * APAD + c) = make_uint2(pk_h2(lx, ly), pk_h2(lz, lw));
        }
#pragma unroll
        for (int it = 0; it < 2; it++) {
            int i = tid + (it << 8);
            int r = i >> 2, c = (i & 3) << 3;
            *(uint4*)(sb_hi + r * APAD + c) = pbh[it];
            *(uint4*)(sb_lo + r * APAD + c) = pbl[it];
        }
    };

    float acc[4][4][4] = {};

    // ldmatrix per-lane source coordinates
    const int a_row = wm * 64 + (lid & 7) + ((lid >> 3) & 1) * 8;
    const int a_kq = (lid >> 4) * 8;
    const int b_row = wn * 32 + (lid & 7) + (lid >> 4) * 8;
    const int b_kq = ((lid >> 3) & 1) * 8;

    auto COMPUTE = [&](int s) {
        const uint32_t sA = smb + s * STAGE_BYTES;
        const uint32_t sB = sA + 2 * SA_BYTES;
#pragma unroll
        for (int kk = 0; kk < 2; kk++) {
            uint32_t ah[4][4], al[4][4], bh[2][4], bl[2][4];
#pragma unroll
            for (int mt = 0; mt < 4; mt++) {
                uint32_t ad = sA + (uint32_t)(((a_row + mt * 16) * APAD) + kk * 16 + a_kq) * 2;
                ldsm_x4(ah[mt], ad);
                ldsm_x4(al[mt], ad + SA_BYTES);
            }
#pragma unroll
            for (int p = 0; p < 2; p++) {
                uint32_t bd = sB + (uint32_t)(((b_row + p * 16) * APAD) + kk * 16 + b_kq) * 2;
                ldsm_x4(bh[p], bd);
                ldsm_x4(bl[p], bd + SA_BYTES);
            }
#pragma unroll
            for (int mt = 0; mt < 4; mt++)
#pragma unroll
                for (int nt = 0; nt < 4; nt++) {
                    const uint32_t* bhf = &bh[nt >> 1][(nt & 1) * 2];
                    const uint32_t* blf = &bl[nt >> 1][(nt & 1) * 2];
                    mma16816(acc[mt][nt], ah[mt], bhf);
                    mma16816(acc[mt][nt], ah[mt], blf);
                    mma16816(acc[mt][nt], al[mt], bhf);
                }
        }
    };

    const int nch = K >> 5;
    LOAD(0);
    STORE(0);
    __syncthreads();
    for (int ch = 0; ch < nch; ch++) {
        const int s = ch & 1;
        if (ch + 1 < nch) LOAD(ch + 1);
        COMPUTE(s);
        if (ch + 1 < nch) STORE(s ^ 1);
        __syncthreads();
    }

    // epilogue: direct float2 stores with bias (+relu)
    const int er = bm + wm * 64 + (lid >> 2);
    const int ec = bn + wn * 32 + (lid & 3) * 2;
#pragma unroll
    for (int mt = 0; mt < 4; mt++)
#pragma unroll
        for (int nt = 0; nt < 4; nt++) {
            int r0 = er + mt * 16, c0 = ec + nt * 8;
            float2 b2 = *(const float2*)(bias + c0);
            float2 v0 = make_float2(acc[mt][nt][0] + b2.x, acc[mt][nt][1] + b2.y);
            float2 v1 = make_float2(acc[mt][nt][2] + b2.x, acc[mt][nt][3] + b2.y);
            if (RELU) {
                v0.x = fmaxf(v0.x, 0.f); v0.y = fmaxf(v0.y, 0.f);
                v1.x = fmaxf(v1.x, 0.f); v1.y = fmaxf(v1.y, 0.f);
            }
            *(float2*)(C + (size_t)r0 * ldc + c0) = v0;
            *(float2*)(C + (size_t)(r0 + 8) * ldc + c0) = v1;
        }
}

// ---------------- embedding + positional encoding ----------------
__global__ void embed_kernel(const int* __restrict__ tok,
                             const float* __restrict__ emb,
                             const float* __restrict__ pos,
                             float* __restrict__ out) {
    int i = blockIdx.x * blockDim.x + threadIdx.x;
    int d = i & (kD - 1);
    int t = i >> 9;
    int s = t & (kS - 1);
    out[i] = emb[(size_t)tok[t] * kD + d] + pos[s * kD + d];
}

// ---------------- attention scores (fp32, strided Q/K) ----------------
__global__ __launch_bounds__(256)
void attn_scores_kernel(const float* __restrict__ Q, const float* __restrict__ Kmat,
                        float* __restrict__ Sc, int ldq, int ldk) {
    const int bh = blockIdx.z;
    const int b = bh >> 3, h = bh & 7;
    const int q0 = blockIdx.y << 6, k0 = blockIdx.x << 6;

    __shared__ float Qs[64][64];
    __shared__ float Ks[64][64];

    const int tid = threadIdx.x;
    const float* Qb = Q + (size_t)(b * kS + q0) * ldq + h * kDK;
    const float* Kb = Kmat + (size_t)(b * kS + k0) * ldk + h * kDK;

#pragma unroll
    for (int it = 0; it < 4; it++) {
        int idx = tid + (it << 8);
        int row = idx >> 4;
        int c4 = (idx & 15) << 2;
        float4 qv = *(const float4*)(Qb + (size_t)row * ldq + c4);
        Qs[c4 + 0][row] = qv.x; Qs[c4 + 1][row] = qv.y;
        Qs[c4 + 2][row] = qv.z; Qs[c4 + 3][row] = qv.w;
        float4 kv = *(const float4*)(Kb + (size_t)row * ldk + c4);
        Ks[c4 + 0][row] = kv.x; Ks[c4 + 1][row] = kv.y;
        Ks[c4 + 2][row] = kv.z; Ks[c4 + 3][row] = kv.w;
    }
    __syncthreads();

    const int tx = tid & 15, ty = tid >> 4;
    float acc[4][4] = {};
#pragma unroll
    for (int kk = 0; kk < 64; kk++) {
        float4 a4 = *(const float4*)&Qs[kk][ty << 2];
        float4 b4 = *(const float4*)&Ks[kk][tx << 2];
        float ra[4] = {a4.x, a4.y, a4.z, a4.w};
        float rb[4] = {b4.x, b4.y, b4.z, b4.w};
#pragma unroll
        for (int i = 0; i < 4; i++)
#pragma unroll
            for (int j = 0; j < 4; j++)
                acc[i][j] = fmaf(ra[i], rb[j], acc[i][j]);
    }

#pragma unroll
    for (int i = 0; i < 4; i++) {
        float out[4] = {acc[i][0] * kSCALE, acc[i][1] * kSCALE,
                        acc[i][2] * kSCALE, acc[i][3] * kSCALE};
        float* Sp = Sc + ((size_t)bh * kS + q0 + (ty << 2) + i) * kS + k0 + (tx << 2);
        *(float4*)Sp = *(float4*)out;
    }
}

// ---------------- masked softmax ----------------
__global__ __launch_bounds__(128)
void softmax_kernel(float* __restrict__ Sc, const int* __restrict__ qtok,
                    const int* __restrict__ ktok, int mode) {
    const int r = blockIdx.x;
    const int q = r & (kS - 1);
    const int bh = r >> 9;
    const int b = bh >> 3;
    float* row = Sc + (size_t)r * kS;
    const int tid = threadIdx.x;

    bool qvalid = true;
    if (mode == 1) qvalid = (qtok[b * kS + q] != 0);

    float v[4];
#pragma unroll
    for (int i = 0; i < 4; i++) {
        int k = tid + (i << 7);
        float s = row[k];
        bool valid = (mode == 0) ? (ktok[b * kS + k] != 0) : (qvalid && (k <= q));
        v[i] = valid ? s : kNEG;
    }

    __shared__ float red[4];
    float m = fmaxf(fmaxf(v[0], v[1]), fmaxf(v[2], v[3]));
    for (int o = 16; o; o >>= 1) m = fmaxf(m, __shfl_xor_sync(0xffffffffu, m, o));
    if ((tid & 31) == 0) red[tid >> 5] = m;
    __syncthreads();
    m = fmaxf(fmaxf(red[0], red[1]), fmaxf(red[2], red[3]));
    __syncthreads();

    float sum = 0.0f;
#pragma unroll
    for (int i = 0; i < 4; i++) { v[i] = expf(v[i] - m); sum += v[i]; }
    for (int o = 16; o; o >>= 1) sum += __shfl_xor_sync(0xffffffffu, sum, o);
    if ((tid & 31) == 0) red[tid >> 5] = sum;
    __syncthreads();
    sum = red[0] + red[1] + red[2] + red[3];

    float inv = 1.0f / sum;
#pragma unroll
    for (int i = 0; i < 4; i++) row[tid + (i << 7)] = v[i] * inv;
}

// ---------------- PV (fp32, strided V) ----------------
__global__ __launch_bounds__(256)
void attn_pv_kernel(const float* __restrict__ P, const float* __restrict__ V,
                    float* __restrict__ O, int ldv) {
    const int bh = blockIdx.y;
    const int b = bh >> 3, h = bh & 7;
    const int q0 = blockIdx.x << 6;

    __shared__ float Ps[16][64];
    __shared__ float Vs[16][64];

    const int tid = threadIdx.x;
    const int tx = tid & 15, ty = tid >> 4;
    const float* Pb = P + (size_t)bh * kS * kS + (size_t)q0 * kS;
    const float* Vb = V + (size_t)(b * kS) * ldv + h * kDK;

    const int pq = tid >> 2, pc = (tid & 3) << 2;
    const int vk = tid >> 4, vc = (tid & 15) << 2;

    float acc[4][4] = {};
    for (int k0 = 0; k0 < kS; k0 += 16) {
        float4 pv = *(const float4*)(Pb + (size_t)pq * kS + k0 + pc);
        Ps[pc + 0][pq] = pv.x; Ps[pc + 1][pq] = pv.y;
        Ps[pc + 2][pq] = pv.z; Ps[pc + 3][pq] = pv.w;
        *(float4*)&Vs[vk][vc] = *(const float4*)(Vb + (size_t)(k0 + vk) * ldv + vc);
        __syncthreads();
#pragma unroll
        for (int kk = 0; kk < 16; kk++) {
            float4 a4 = *(const float4*)&Ps[kk][ty << 2];
            float4 b4 = *(const float4*)&Vs[kk][tx << 2];
            float ra[4] = {a4.x, a4.y, a4.z, a4.w};
            float rb[4] = {b4.x, b4.y, b4.z, b4.w};
#pragma unroll
            for (int i = 0; i < 4; i++)
#pragma unroll
                for (int j = 0; j < 4; j++)
                    acc[i][j] = fmaf(ra[i], rb[j], acc[i][j]);
        }
        __syncthreads();
    }

#pragma unroll
    for (int i = 0; i < 4; i++) {
        float out[4] = {acc[i][0], acc[i][1], acc[i][2], acc[i][3]};
        float* Op = O + (size_t)(b * kS + q0 + (ty << 2) + i) * kD + h * kDK + (tx << 2);
        *(float4*)Op = *(float4*)out;
    }
}

// ---------------- x = LayerNorm(x + a) * g + b ----------------
__global__ __launch_bounds__(128)
void add_ln_kernel(float* __restrict__ x, const float* __restrict__ a,
                   const float* __restrict__ g, const float* __restrict__ bet) {
    const int r = blockIdx.x;
    const int tid = threadIdx.x;
    __shared__ float red[4];

    float v[4];
#pragma unroll
    for (int i = 0; i < 4; i++) {
        int c = tid + (i << 7);
        size_t idx = (size_t)r * kD + c;
        v[i] = x[idx] + a[idx];
    }

    float s = v[0] + v[1] + v[2] + v[3];
    for (int o = 16; o; o >>= 1) s += __shfl_xor_sync(0xffffffffu, s, o);
    if ((tid & 31) == 0) red[tid >> 5] = s;
    __syncthreads();
    s = red[0] + red[1] + red[2] + red[3];
    __syncthreads();
    const float mu = s * (1.0f / kD);

    float sq = 0.0f;
#pragma unroll
    for (int i = 0; i < 4; i++) { float d = v[i] - mu; sq += d * d; }
    for (int o = 16; o; o >>= 1) sq += __shfl_xor_sync(0xffffffffu, sq, o);
    if ((tid & 31) == 0) red[tid >> 5] = sq;
    __syncthreads();
    sq = red[0] + red[1] + red[2] + red[3];
    const float rstd = rsqrtf(sq * (1.0f / kD) + kEPS);

#pragma unroll
    for (int i = 0; i < 4; i++) {
        int c = tid + (i << 7);
        x[(size_t)r * kD + c] = (v[i] - mu) * rstd * g[c] + bet[c];
    }
}

// ---------------- host-side orchestration ----------------------------------
static void hgemm(const float* A, const __half* bhi, const __half* blo,
                  const float* bias, float* C, int M, int N, int K, int ldc,
                  bool relu) {
    dim3 grid(N / 128, M / 128);
    if (relu) hgemm_kernel<true><<<grid, 256, HG_SMEM>>>(A, bhi, blo, bias, C, M, N, K, ldc);
    else      hgemm_kernel<false><<<grid, 256, HG_SMEM>>>(A, bhi, blo, bias, C, M, N, K, ldc);
}

// Self-attention: fused QKV projection (weights q,k,v contiguous in [N,K]).
static void attn_core(float* qkv, float* ctx, float* sc,
                      const int* qtok, const int* ktok, int mode) {
    attn_scores_kernel<<<dim3(kS / 64, kS / 64, kB * kH), 256>>>(
        qkv, qkv + kD, sc, 3 * kD, 3 * kD);
    softmax_kernel<<<kB * kH * kS, 128>>>(sc, qtok, ktok, mode);
    attn_pv_kernel<<<dim3(kS / 64, kB * kH), 256>>>(sc, qkv + 2 * kD, ctx, 3 * kD);
}

extern "C" void kernel_launch(void* const* d_in, const int* in_sizes, int n_in,
                              void* d_out, int out_size) {
    const int*   src     = (const int*)d_in[0];
    const int*   tgt     = (const int*)d_in[1];
    const float* enc_emb = (const float*)d_in[2];
    const float* dec_emb = (const float*)d_in[3];
    const float* pos     = (const float*)d_in[4];
    const float* enc_aw  = (const float*)d_in[5];
    const float* enc_ab  = (const float*)d_in[6];
    const float* enc_w1  = (const float*)d_in[7];
    const float* enc_b1  = (const float*)d_in[8];
    const float* enc_w2  = (const float*)d_in[9];
    const float* enc_b2  = (const float*)d_in[10];
    const float* enc_lng = (const float*)d_in[11];
    const float* enc_lnb = (const float*)d_in[12];
    const float* dec_aw  = (const float*)d_in[13];
    const float* dec_ab  = (const float*)d_in[14];
    const float* dec_w1  = (const float*)d_in[15];
    const float* dec_b1  = (const float*)d_in[16];
    const float* dec_w2  = (const float*)d_in[17];
    const float* dec_b2  = (const float*)d_in[18];
    const float* dec_lng = (const float*)d_in[19];
    const float* dec_lnb = (const float*)d_in[20];
    const float* fc_w    = (const float*)d_in[21];
    const float* fc_b    = (const float*)d_in[22];

    float *x, *y, *qkv, *ctx, *t, *ffn, *sc;
    __half *whi, *wlo;
    cudaGetSymbolAddress((void**)&x,   g_x);
    cudaGetSymbolAddress((void**)&y,   g_y);
    cudaGetSymbolAddress((void**)&qkv, g_qkv);
    cudaGetSymbolAddress((void**)&ctx, g_ctx);
    cudaGetSymbolAddress((void**)&t,   g_t);
    cudaGetSymbolAddress((void**)&ffn, g_ffn);
    cudaGetSymbolAddress((void**)&sc,  g_sc);
    cudaGetSymbolAddress((void**)&whi, g_whi);
    cudaGetSymbolAddress((void**)&wlo, g_wlo);

    cudaFuncSetAttribute(hgemm_kernel<false>, cudaFuncAttributeMaxDynamicSharedMemorySize, HG_SMEM);
    cudaFuncSetAttribute(hgemm_kernel<true>,  cudaFuncAttributeMaxDynamicSharedMemorySize, HG_SMEM);

    // ---------------- weight conversion (transpose + fp16 hi/lo) -----------
    for (int i = 0; i < 24; i++)
        wconv_kernel<<<dim3(16, 16), 256>>>(enc_aw + (size_t)i * DD,
                                            whi + OFF_EA + i * DD, wlo + OFF_EA + i * DD, kD, kD);
    for (int i = 0; i < 48; i++)
        wconv_kernel<<<dim3(16, 16), 256>>>(dec_aw + (size_t)i * DD,
                                            whi + OFF_DA + i * DD, wlo + OFF_DA + i * DD, kD, kD);
    for (int l = 0; l < kL; l++) {
        wconv_kernel<<<dim3(64, 16), 256>>>(enc_w1 + (size_t)l * DF,
                                            whi + OFF_EW1 + l * DF, wlo + OFF_EW1 + l * DF, kD, kF);
        wconv_kernel<<<dim3(16, 64), 256>>>(enc_w2 + (size_t)l * DF,
                                            whi + OFF_EW2 + l * DF, wlo + OFF_EW2 + l * DF, kF, kD);
        wconv_kernel<<<dim3(64, 16), 256>>>(dec_w1 + (size_t)l * DF,
                                            whi + OFF_DW1 + l * DF, wlo + OFF_DW1 + l * DF, kD, kF);
        wconv_kernel<<<dim3(16, 64), 256>>>(dec_w2 + (size_t)l * DF,
                                            whi + OFF_DW2 + l * DF, wlo + OFF_DW2 + l * DF, kF, kD);
    }
    wconv_kernel<<<dim3(1000, 16), 256>>>(fc_w, whi + OFF_FC, wlo + OFF_FC, kD, kV);

    const int embBlocks = (kNT * kD) / 256;

    // ---------------- encoder ----------------
    embed_kernel<<<embBlocks, 256>>>(src, enc_emb, pos, x);
    for (int l = 0; l < kL; l++) {
        const __half* wh = whi + OFF_EA + (size_t)l * 4 * DD;
        const __half* wl = wlo + OFF_EA + (size_t)l * 4 * DD;
        const float* Wb = enc_ab + (size_t)l * 4 * kD;
        hgemm(x, wh, wl, Wb, qkv, kNT, 3 * kD, kD, 3 * kD, false);     // fused QKV
        attn_core(qkv, ctx, sc, nullptr, src, 0);
        hgemm(ctx, wh + 3 * DD, wl + 3 * DD, Wb + 3 * kD, t, kNT, kD, kD, kD, false);
        add_ln_kernel<<<kNT, 128>>>(x, t, enc_lng + (size_t)(l * 2 + 0) * kD,
                                    enc_lnb + (size_t)(l * 2 + 0) * kD);
        hgemm(x, whi + OFF_EW1 + (size_t)l * DF, wlo + OFF_EW1 + (size_t)l * DF,
              enc_b1 + (size_t)l * kF, ffn, kNT, kF, kD, kF, true);
        hgemm(ffn, whi + OFF_EW2 + (size_t)l * DF, wlo + OFF_EW2 + (size_t)l * DF,
              enc_b2 + (size_t)l * kD, t, kNT, kD, kF, kD, false);
        add_ln_kernel<<<kNT, 128>>>(x, t, enc_lng + (size_t)(l * 2 + 1) * kD,
                                    enc_lnb + (size_t)(l * 2 + 1) * kD);
    }

    // ---------------- decoder ----------------
    embed_kernel<<<embBlocks, 256>>>(tgt, dec_emb, pos, y);
    for (int l = 0; l < kL; l++) {
        const __half* wh = whi + OFF_DA + (size_t)l * 8 * DD;
        const __half* wl = wlo + OFF_DA + (size_t)l * 8 * DD;
        const float* Wb = dec_ab + (size_t)l * 8 * kD;
        // self-attention (fused QKV, causal + query-validity mask)
        hgemm(y, wh, wl, Wb, qkv, kNT, 3 * kD, kD, 3 * kD, false);
        attn_core(qkv, ctx, sc, tgt, tgt, 1);
        hgemm(ctx, wh + 3 * DD, wl + 3 * DD, Wb + 3 * kD, t, kNT, kD, kD, kD, false);
        add_ln_kernel<<<kNT, 128>>>(y, t, dec_lng + (size_t)(l * 3 + 0) * kD,
                                    dec_lnb + (size_t)(l * 3 + 0) * kD);
        // cross-attention: q from y, fused KV from enc_out x
        hgemm(y, wh + 4 * DD, wl + 4 * DD, Wb + 4 * kD, qkv, kNT, kD, kD, 3 * kD, false);
        hgemm(x, wh + 5 * DD, wl + 5 * DD, Wb + 5 * kD, qkv + kD, kNT, 2 * kD, kD, 3 * kD, false);
        attn_core(qkv, ctx, sc, nullptr, src, 0);
        hgemm(ctx, wh + 7 * DD, wl + 7 * DD, Wb + 7 * kD, t, kNT, kD, kD, kD, false);
        add_ln_kernel<<<kNT, 128>>>(y, t, dec_lng + (size_t)(l * 3 + 1) * kD,
                                    dec_lnb + (size_t)(l * 3 + 1) * kD);
        // FFN
        hgemm(y, whi + OFF_DW1 + (size_t)l * DF, wlo + OFF_DW1 + (size_t)l * DF,
              dec_b1 + (size_t)l * kF, ffn, kNT, kF, kD, kF, true);
        hgemm(ffn, whi + OFF_DW2 + (size_t)l * DF, wlo + OFF_DW2 + (size_t)l * DF,
              dec_b2 + (size_t)l * kD, t, kNT, kD, kF, kD, false);
        add_ln_kernel<<<kNT, 128>>>(y, t, dec_lng + (size_t)(l * 3 + 2) * kD,
                                    dec_lnb + (size_t)(l * 3 + 2) * kD);
    }

    // ---------------- final projection to vocab ----------------
    hgemm(y, whi + OFF_FC, wlo + OFF_FC, fc_b, (float*)d_out, kNT, kV, kD, kV, false);
}

// round 4
// speedup vs baseline: 2.7163x; 1.4531x over previous
#include <cuda_runtime.h>
#include <cuda_fp16.h>
#include <cstddef>
#include <cstdint>

// ---------------- problem constants ----------------
constexpr int kB = 8;
constexpr int kS = 512;
constexpr int kD = 512;
constexpr int kH = 8;
constexpr int kDK = 64;
constexpr int kL = 6;
constexpr int kF = 2048;
constexpr int kV = 32000;
constexpr int kNT = kB * kS;
constexpr float kNEG = -1e9f;
constexpr float kEPS = 1e-5f;
constexpr float kSCALE = 0.125f;

// ---------------- fp16 weight scratch layout (transposed to [N,K]) ---------
constexpr size_t DD  = (size_t)kD * kD;
constexpr size_t DF  = (size_t)kD * kF;
constexpr size_t OFF_EA  = 0;
constexpr size_t OFF_DA  = OFF_EA  + 24 * DD;
constexpr size_t OFF_EW1 = OFF_DA  + 48 * DD;
constexpr size_t OFF_EW2 = OFF_EW1 + 6 * DF;
constexpr size_t OFF_DW1 = OFF_EW2 + 6 * DF;
constexpr size_t OFF_DW2 = OFF_DW1 + 6 * DF;
constexpr size_t OFF_FC  = OFF_DW2 + 6 * DF;
constexpr size_t W_TOTAL = OFF_FC + (size_t)kV * kD;

// ---------------- device scratch ----------------
__device__ float g_x[kNT * kD];
__device__ float g_y[kNT * kD];
__device__ float g_qkv[kNT * 3 * kD];
__device__ float g_ctx[kNT * kD];
__device__ float g_t[kNT * kD];
__device__ float g_ffn[kNT * kF];
__device__ __half g_whi[W_TOTAL];
__device__ __half g_wlo[W_TOTAL];

// ========================= helpers ==========================================
__device__ __forceinline__ uint32_t smem_u32(const void* p) {
    uint32_t a;
    asm("{ .reg .u64 t; cvta.to.shared.u64 t, %1; cvt.u32.u64 %0, t; }"
        : "=r"(a) : "l"(p));
    return a;
}

__device__ __forceinline__ void ldsm_x4(uint32_t (&r)[4], uint32_t addr) {
    asm volatile("ldmatrix.sync.aligned.m8n8.x4.shared.b16 {%0,%1,%2,%3}, [%4];"
                 : "=r"(r[0]), "=r"(r[1]), "=r"(r[2]), "=r"(r[3]) : "r"(addr));
}
__device__ __forceinline__ void ldsm_x4_t(uint32_t (&r)[4], uint32_t addr) {
    asm volatile("ldmatrix.sync.aligned.m8n8.x4.trans.shared.b16 {%0,%1,%2,%3}, [%4];"
                 : "=r"(r[0]), "=r"(r[1]), "=r"(r[2]), "=r"(r[3]) : "r"(addr));
}

__device__ __forceinline__ void mma16816(float (&c)[4], const uint32_t (&a)[4],
                                         const uint32_t* b) {
    asm volatile(
        "mma.sync.aligned.m16n8k16.row.col.f32.f16.f16.f32 "
        "{%0,%1,%2,%3}, {%4,%5,%6,%7}, {%8,%9}, {%0,%1,%2,%3};"
        : "+f"(c[0]), "+f"(c[1]), "+f"(c[2]), "+f"(c[3])
        : "r"(a[0]), "r"(a[1]), "r"(a[2]), "r"(a[3]), "r"(b[0]), "r"(b[1]));
}

__device__ __forceinline__ uint32_t pk_h2(__half a, __half b) {
    __half2 t = __halves2half2(a, b);
    return *reinterpret_cast<uint32_t*>(&t);
}

// ============== batched weight transpose + fp16 hi/lo split =================
__global__ __launch_bounds__(256)
void wconv_kernel(const float* __restrict__ W, __half* __restrict__ hi,
                  __half* __restrict__ lo, int K, int N) {
    const size_t moff = (size_t)blockIdx.z * K * N;
    W += moff; hi += moff; lo += moff;
    __shared__ float t[32][33];
    const int n0 = blockIdx.x << 5, k0 = blockIdx.y << 5;
    const int tx = threadIdx.x & 31, ty = threadIdx.x >> 5;
#pragma unroll
    for (int j = 0; j < 32; j += 8)
        t[ty + j][tx] = W[(size_t)(k0 + ty + j) * N + n0 + tx];
    __syncthreads();
#pragma unroll
    for (int j = 0; j < 32; j += 8) {
        float v = t[tx][ty + j];
        __half h = __float2half_rn(v);
        __half l = __float2half_rn(v - __half2float(h));
        size_t o = (size_t)(n0 + ty + j) * K + k0 + tx;
        hi[o] = h;
        lo[o] = l;
    }
}

// ======== HMMA GEMM (unchanged from round 3) ================================
constexpr int APAD = 40;
constexpr int SA_BYTES = 128 * APAD * 2;
constexpr int STAGE_BYTES = 4 * SA_BYTES;
constexpr int HG_SMEM = 2 * STAGE_BYTES;

template <bool RELU>
__global__ __launch_bounds__(256)
void hgemm_kernel(const float* __restrict__ A,
                  const __half* __restrict__ Bhi,
                  const __half* __restrict__ Blo,
                  const float* __restrict__ bias,
                  float* __restrict__ C,
                  int M, int N, int K, int ldc) {
    extern __shared__ char sm[];
    const int tid = threadIdx.x;
    const int lid = tid & 31, wid = tid >> 5;
    const int wm = wid >> 2, wn = wid & 3;
    const int bm = blockIdx.y << 7, bn = blockIdx.x << 7;
    const uint32_t smb = smem_u32(sm);

    const float*  Ap  = A   + (size_t)bm * K;
    const __half* Bhp = Bhi + (size_t)bn * K;
    const __half* Blp = Blo + (size_t)bn * K;

    float4 pa[4];
    uint4 pbh[2], pbl[2];

    auto LOAD = [&](int ch) {
#pragma unroll
        for (int it = 0; it < 4; it++) {
            int i = tid + (it << 8);
            int r = i >> 3, c = (i & 7) << 2;
            pa[it] = *(const float4*)(Ap + (size_t)r * K + ch * 32 + c);
        }
#pragma unroll
        for (int it = 0; it < 2; it++) {
            int i = tid + (it << 8);
            int r = i >> 2, c = (i & 3) << 3;
            pbh[it] = *(const uint4*)(Bhp + (size_t)r * K + ch * 32 + c);
            pbl[it] = *(const uint4*)(Blp + (size_t)r * K + ch * 32 + c);
        }
    };

    auto STORE = [&](int s) {
        __half* sa_hi = (__half*)(sm + s * STAGE_BYTES);
        __half* sa_lo = (__half*)(sm + s * STAGE_BYTES + SA_BYTES);
        __half* sb_hi = (__half*)(sm + s * STAGE_BYTES + 2 * SA_BYTES);
        __half* sb_lo = (__half*)(sm + s * STAGE_BYTES + 3 * SA_BYTES);
#pragma unroll
        for (int it = 0; it < 4; it++) {
            int i = tid + (it << 8);
            int r = i >> 3, c = (i & 7) << 2;
            float4 v = pa[it];
            __half hx = __float2half_rn(v.x), hy = __float2half_rn(v.y);
            __half hz = __float2half_rn(v.z), hw = __float2half_rn(v.w);
            __half lx = __float2half_rn(v.x - __half2float(hx));
            __half ly = __float2half_rn(v.y - __half2float(hy));
            __half lz = __float2half_rn(v.z - __half2float(hz));
            __half lw = __float2half_rn(v.w - __half2float(hw));
            *(uint2*)(sa_hi + r * APAD + c) = make_uint2(pk_h2(hx, hy), pk_h2(hz, hw));
            *(uint2*)(sa_lo + r * APAD + c) = make_uint2(pk_h2(lx, ly), pk_h2(lz, lw));
        }
#pragma unroll
        for (int it = 0; it < 2; it++) {
            int i = tid + (it << 8);
            int r = i >> 2, c = (i & 3) << 3;
            *(uint4*)(sb_hi + r * APAD + c) = pbh[it];
            *(uint4*)(sb_lo + r * APAD + c) = pbl[it];
        }
    };

    float acc[4][4][4] = {};

    const int a_row = wm * 64 + (lid & 7) + ((lid >> 3) & 1) * 8;
    const int a_kq = (lid >> 4) * 8;
    const int b_row = wn * 32 + (lid & 7) + (lid >> 4) * 8;
    const int b_kq = ((lid >> 3) & 1) * 8;

    auto COMPUTE = [&](int s) {
        const uint32_t sA = smb + s * STAGE_BYTES;
        const uint32_t sB = sA + 2 * SA_BYTES;
#pragma unroll
        for (int kk = 0; kk < 2; kk++) {
            uint32_t ah[4][4], al[4][4], bh[2][4], bl[2][4];
#pragma unroll
            for (int mt = 0; mt < 4; mt++) {
                uint32_t ad = sA + (uint32_t)(((a_row + mt * 16) * APAD) + kk * 16 + a_kq) * 2;
                ldsm_x4(ah[mt], ad);
                ldsm_x4(al[mt], ad + SA_BYTES);
            }
#pragma unroll
            for (int p = 0; p < 2; p++) {
                uint32_t bd = sB + (uint32_t)(((b_row + p * 16) * APAD) + kk * 16 + b_kq) * 2;
                ldsm_x4(bh[p], bd);
                ldsm_x4(bl[p], bd + SA_BYTES);
            }
#pragma unroll
            for (int mt = 0; mt < 4; mt++)
#pragma unroll
                for (int nt = 0; nt < 4; nt++) {
                    const uint32_t* bhf = &bh[nt >> 1][(nt & 1) * 2];
                    const uint32_t* blf = &bl[nt >> 1][(nt & 1) * 2];
                    mma16816(acc[mt][nt], ah[mt], bhf);
                    mma16816(acc[mt][nt], ah[mt], blf);
                    mma16816(acc[mt][nt], al[mt], bhf);
                }
        }
    };

    const int nch = K >> 5;
    LOAD(0);
    STORE(0);
    __syncthreads();
    for (int ch = 0; ch < nch; ch++) {
        const int s = ch & 1;
        if (ch + 1 < nch) LOAD(ch + 1);
        COMPUTE(s);
        if (ch + 1 < nch) STORE(s ^ 1);
        __syncthreads();
    }

    const int er = bm + wm * 64 + (lid >> 2);
    const int ec = bn + wn * 32 + (lid & 3) * 2;
#pragma unroll
    for (int mt = 0; mt < 4; mt++)
#pragma unroll
        for (int nt = 0; nt < 4; nt++) {
            int r0 = er + mt * 16, c0 = ec + nt * 8;
            float2 b2 = *(const float2*)(bias + c0);
            float2 v0 = make_float2(acc[mt][nt][0] + b2.x, acc[mt][nt][1] + b2.y);
            float2 v1 = make_float2(acc[mt][nt][2] + b2.x, acc[mt][nt][3] + b2.y);
            if (RELU) {
                v0.x = fmaxf(v0.x, 0.f); v0.y = fmaxf(v0.y, 0.f);
                v1.x = fmaxf(v1.x, 0.f); v1.y = fmaxf(v1.y, 0.f);
            }
            *(float2*)(C + (size_t)r0 * ldc + c0) = v0;
            *(float2*)(C + (size_t)(r0 + 8) * ldc + c0) = v1;
        }
}

// ================= fused flash attention (HMMA fp16 hi/lo 3-pass) ===========
// grid (kS/64, kB*kH), 128 threads (4 warps x 16 q-rows).
// mode 0: key mask from ktok; mode 1: causal + query-validity (qtok).
constexpr int FAP = 72;                         // halfs per smem row
constexpr int FA_TILE = 64 * FAP;               // halfs per tile plane
constexpr int FA_SMEM = 6 * FA_TILE * 2 + 512 * 4;

__global__ __launch_bounds__(128)
void flash_kernel(const float* __restrict__ Qp, const float* __restrict__ Kp,
                  const float* __restrict__ Vp, float* __restrict__ O,
                  const int* __restrict__ qtok, const int* __restrict__ ktok,
                  int mode) {
    extern __shared__ char sm[];
    __half* sQh = (__half*)sm;
    __half* sQl = sQh + FA_TILE;
    __half* sKh = sQl + FA_TILE;
    __half* sKl = sKh + FA_TILE;
    __half* sVh = sKl + FA_TILE;
    __half* sVl = sVh + FA_TILE;
    float* maskf = (float*)(sVl + FA_TILE);     // 512 floats: 1=valid 0=masked

    const int tid = threadIdx.x, lid = tid & 31, w = tid >> 5;
    const int bh = blockIdx.y, b = bh >> 3, h = bh & 7;
    const int q0 = blockIdx.x << 6;
    const uint32_t smb = smem_u32(sm);
    const uint32_t QH_O = 0, QL_O = FA_TILE * 2, KH_O = 2 * FA_TILE * 2,
                   KL_O = 3 * FA_TILE * 2, VH_O = 4 * FA_TILE * 2,
                   VL_O = 5 * FA_TILE * 2;

    if (mode == 0) {
        for (int i = tid; i < kS; i += 128)
            maskf[i] = (ktok[b * kS + i] != 0) ? 1.0f : 0.0f;
    }

    // ---- load + split Q tile (64 x 64) ----
    {
        const float* Qb = Qp + (size_t)(b * kS + q0) * 1536 + h * kDK;
#pragma unroll
        for (int it = 0; it < 8; it++) {
            int i = tid + (it << 7);
            int r = i >> 4, c4 = (i & 15) << 2;
            float4 v = *(const float4*)(Qb + (size_t)r * 1536 + c4);
            __half hx = __float2half_rn(v.x), hy = __float2half_rn(v.y);
            __half hz = __float2half_rn(v.z), hw = __float2half_rn(v.w);
            __half lx = __float2half_rn(v.x - __half2float(hx));
            __half ly = __float2half_rn(v.y - __half2float(hy));
            __half lz = __float2half_rn(v.z - __half2float(hz));
            __half lw = __float2half_rn(v.w - __half2float(hw));
            *(uint2*)(sQh + r * FAP + c4) = make_uint2(pk_h2(hx, hy), pk_h2(hz, hw));
            *(uint2*)(sQl + r * FAP + c4) = make_uint2(pk_h2(lx, ly), pk_h2(lz, lw));
        }
    }

    float m0 = -1e30f, m1 = -1e30f, l0 = 0.f, l1 = 0.f;
    float o[8][4] = {};

    const int qg0 = q0 + w * 16 + (lid >> 2);
    const int qg1 = qg0 + 8;
    bool qv0 = true, qv1 = true;
    if (mode == 1) {
        qv0 = qtok[b * kS + qg0] != 0;
        qv1 = qtok[b * kS + qg1] != 0;
    }
    // causal skip is only exact if every q-row in this CTA is valid
    const int anyinv = __syncthreads_or(mode == 1 && (!qv0 || !qv1));
    const int ktmax = (mode == 1 && !anyinv) ? blockIdx.x : (kS / 64 - 1);

    const int a_row = (lid & 7) + ((lid >> 3) & 1) * 8;
    const int a_kq = (lid >> 4) * 8;
    const int b_row = (lid & 7) + (lid >> 4) * 8;
    const int b_kq = ((lid >> 3) & 1) * 8;
    const int v_row = (lid & 7) + ((lid >> 3) & 1) * 8;
    const int v_col8 = (lid >> 4) * 8;

    for (int kt = 0; kt <= ktmax; kt++) {
        // ---- load + split K, V tiles ----
        const float* Kb = Kp + (size_t)(b * kS + kt * 64) * 1536 + h * kDK;
        const float* Vb = Vp + (size_t)(b * kS + kt * 64) * 1536 + h * kDK;
#pragma unroll
        for (int it = 0; it < 8; it++) {
            int i = tid + (it << 7);
            int r = i >> 4, c4 = (i & 15) << 2;
            float4 kv = *(const float4*)(Kb + (size_t)r * 1536 + c4);
            float4 vv = *(const float4*)(Vb + (size_t)r * 1536 + c4);
            __half khx = __float2half_rn(kv.x), khy = __float2half_rn(kv.y);
            __half khz = __float2half_rn(kv.z), khw = __float2half_rn(kv.w);
            *(uint2*)(sKh + r * FAP + c4) = make_uint2(pk_h2(khx, khy), pk_h2(khz, khw));
            *(uint2*)(sKl + r * FAP + c4) = make_uint2(
                pk_h2(__float2half_rn(kv.x - __half2float(khx)),
                      __float2half_rn(kv.y - __half2float(khy))),
                pk_h2(__float2half_rn(kv.z - __half2float(khz)),
                      __float2half_rn(kv.w - __half2float(khw))));
            __half vhx = __float2half_rn(vv.x), vhy = __float2half_rn(vv.y);
            __half vhz = __float2half_rn(vv.z), vhw = __float2half_rn(vv.w);
            *(uint2*)(sVh + r * FAP + c4) = make_uint2(pk_h2(vhx, vhy), pk_h2(vhz, vhw));
            *(uint2*)(sVl + r * FAP + c4) = make_uint2(
                pk_h2(__float2half_rn(vv.x - __half2float(vhx)),
                      __float2half_rn(vv.y - __half2float(vhy))),
                pk_h2(__float2half_rn(vv.z - __half2float(vhz)),
                      __float2half_rn(vv.w - __half2float(vhw))));
        }
        __syncthreads();

        // ---- S = Q K^T (3-pass) ----
        float s[8][4] = {};
#pragma unroll
        for (int kk = 0; kk < 4; kk++) {
            uint32_t ah[4], al[4];
            uint32_t ad = smb + QH_O + (uint32_t)(((w * 16 + a_row) * FAP) + kk * 16 + a_kq) * 2;
            ldsm_x4(ah, ad);
            ldsm_x4(al, ad + (QL_O - QH_O));
#pragma unroll
            for (int p = 0; p < 4; p++) {
                uint32_t bhf[4], blf[4];
                uint32_t bd = smb + KH_O + (uint32_t)(((p * 16 + b_row) * FAP) + kk * 16 + b_kq) * 2;
                ldsm_x4(bhf, bd);
                ldsm_x4(blf, bd + (KL_O - KH_O));
#pragma unroll
                for (int t = 0; t < 2; t++) {
                    mma16816(s[p * 2 + t], ah, &bhf[t * 2]);
                    mma16816(s[p * 2 + t], ah, &blf[t * 2]);
                    mma16816(s[p * 2 + t], al, &bhf[t * 2]);
                }
            }
        }

        // ---- scale + mask + online softmax ----
        float mx0 = -1e30f, mx1 = -1e30f;
#pragma unroll
        for (int j = 0; j < 8; j++) {
            int colb = 8 * j + 2 * (lid & 3);
#pragma unroll
            for (int e = 0; e < 4; e++) {
                int kg = kt * 64 + colb + (e & 1);
                float val = s[j][e] * kSCALE;
                if (mode == 0) {
                    val = (maskf[kg] != 0.0f) ? val : kNEG;
                } else {
                    bool qv = (e < 2) ? qv0 : qv1;
                    int qg = (e < 2) ? qg0 : qg1;
                    val = (qv && kg <= qg) ? val : kNEG;
                }
                s[j][e] = val;
                if (e < 2) mx0 = fmaxf(mx0, val);
                else       mx1 = fmaxf(mx1, val);
            }
        }
        mx0 = fmaxf(mx0, __shfl_xor_sync(0xffffffffu, mx0, 1));
        mx0 = fmaxf(mx0, __shfl_xor_sync(0xffffffffu, mx0, 2));
        mx1 = fmaxf(mx1, __shfl_xor_sync(0xffffffffu, mx1, 1));
        mx1 = fmaxf(mx1, __shfl_xor_sync(0xffffffffu, mx1, 2));

        float mn0 = fmaxf(m0, mx0), mn1 = fmaxf(m1, mx1);
        float al0 = __expf(m0 - mn0), al1 = __expf(m1 - mn1);
        m0 = mn0; m1 = mn1;

        float sum0 = 0.f, sum1 = 0.f;
#pragma unroll
        for (int j = 0; j < 8; j++) {
            s[j][0] = __expf(s[j][0] - mn0); sum0 += s[j][0];
            s[j][1] = __expf(s[j][1] - mn0); sum0 += s[j][1];
            s[j][2] = __expf(s[j][2] - mn1); sum1 += s[j][2];
            s[j][3] = __expf(s[j][3] - mn1); sum1 += s[j][3];
        }
        sum0 += __shfl_xor_sync(0xffffffffu, sum0, 1);
        sum0 += __shfl_xor_sync(0xffffffffu, sum0, 2);
        sum1 += __shfl_xor_sync(0xffffffffu, sum1, 1);
        sum1 += __shfl_xor_sync(0xffffffffu, sum1, 2);
        l0 = l0 * al0 + sum0;
        l1 = l1 * al1 + sum1;

#pragma unroll
        for (int j = 0; j < 8; j++) {
            o[j][0] *= al0; o[j][1] *= al0;
            o[j][2] *= al1; o[j][3] *= al1;
        }

        // ---- O += P V (3-pass) ----
#pragma unroll
        for (int kc = 0; kc < 4; kc++) {
            uint32_t ph[4], pl[4];
#pragma unroll
            for (int half16 = 0; half16 < 2; half16++) {
                int j = 2 * kc + half16;
                __half h0 = __float2half_rn(s[j][0]);
                __half h1 = __float2half_rn(s[j][1]);
                __half h2 = __float2half_rn(s[j][2]);
                __half h3 = __float2half_rn(s[j][3]);
                ph[half16 * 2 + 0] = pk_h2(h0, h1);
                ph[half16 * 2 + 1] = pk_h2(h2, h3);
                pl[half16 * 2 + 0] = pk_h2(__float2half_rn(s[j][0] - __half2float(h0)),
                                           __float2half_rn(s[j][1] - __half2float(h1)));
                pl[half16 * 2 + 1] = pk_h2(__float2half_rn(s[j][2] - __half2float(h2)),
                                           __float2half_rn(s[j][3] - __half2float(h3)));
            }
            // reorder: a-frag wants {row r k0..}, {row r+8 k0..}, {row r k8..}, {row r+8 k8..}
            uint32_t pha[4] = { ph[0], ph[1], ph[2], ph[3] };
            uint32_t pla[4] = { pl[0], pl[1], pl[2], pl[3] };
#pragma unroll
            for (int dp = 0; dp < 4; dp++) {
                uint32_t vh[4], vl[4];
                uint32_t vd = smb + VH_O + (uint32_t)(((kc * 16 + v_row) * FAP) + dp * 16 + v_col8) * 2;
                ldsm_x4_t(vh, vd);
                ldsm_x4_t(vl, vd + (VL_O - VH_O));
#pragma unroll
                for (int t = 0; t < 2; t++) {
                    mma16816(o[dp * 2 + t], pha, &vh[t * 2]);
                    mma16816(o[dp * 2 + t], pha, &vl[t * 2]);
                    mma16816(o[dp * 2 + t], pla, &vh[t * 2]);
                }
            }
        }
        __syncthreads();
    }

    // ---- normalize + store ----
    const float inv0 = 1.0f / l0, inv1 = 1.0f / l1;
    float* O0 = O + (size_t)(b * kS + q0 + w * 16 + (lid >> 2)) * kD + h * kDK;
    float* O1 = O0 + 8 * kD;
#pragma unroll
    for (int j = 0; j < 8; j++) {
        int colb = 8 * j + 2 * (lid & 3);
        *(float2*)(O0 + colb) = make_float2(o[j][0] * inv0, o[j][1] * inv0);
        *(float2*)(O1 + colb) = make_float2(o[j][2] * inv1, o[j][3] * inv1);
    }
}

// ---------------- embedding + positional encoding ----------------
__global__ void embed_kernel(const int* __restrict__ tok,
                             const float* __restrict__ emb,
                             const float* __restrict__ pos,
                             float* __restrict__ out) {
    int i = blockIdx.x * blockDim.x + threadIdx.x;
    int d = i & (kD - 1);
    int t = i >> 9;
    int s = t & (kS - 1);
    out[i] = emb[(size_t)tok[t] * kD + d] + pos[s * kD + d];
}

// ---------------- x = LayerNorm(x + a) * g + b ----------------
__global__ __launch_bounds__(128)
void add_ln_kernel(float* __restrict__ x, const float* __restrict__ a,
                   const float* __restrict__ g, const float* __restrict__ bet) {
    const int r = blockIdx.x;
    const int tid = threadIdx.x;
    __shared__ float red[4];

    float v[4];
#pragma unroll
    for (int i = 0; i < 4; i++) {
        int c = tid + (i << 7);
        size_t idx = (size_t)r * kD + c;
        v[i] = x[idx] + a[idx];
    }

    float s = v[0] + v[1] + v[2] + v[3];
    for (int o = 16; o; o >>= 1) s += __shfl_xor_sync(0xffffffffu, s, o);
    if ((tid & 31) == 0) red[tid >> 5] = s;
    __syncthreads();
    s = red[0] + red[1] + red[2] + red[3];
    __syncthreads();
    const float mu = s * (1.0f / kD);

    float sq = 0.0f;
#pragma unroll
    for (int i = 0; i < 4; i++) { float d = v[i] - mu; sq += d * d; }
    for (int o = 16; o; o >>= 1) sq += __shfl_xor_sync(0xffffffffu, sq, o);
    if ((tid & 31) == 0) red[tid >> 5] = sq;
    __syncthreads();
    sq = red[0] + red[1] + red[2] + red[3];
    const float rstd = rsqrtf(sq * (1.0f / kD) + kEPS);

#pragma unroll
    for (int i = 0; i < 4; i++) {
        int c = tid + (i << 7);
        x[(size_t)r * kD + c] = (v[i] - mu) * rstd * g[c] + bet[c];
    }
}

// ---------------- host-side orchestration ----------------------------------
static void hgemm(const float* A, const __half* bhi, const __half* blo,
                  const float* bias, float* C, int M, int N, int K, int ldc,
                  bool relu) {
    dim3 grid(N / 128, M / 128);
    if (relu) hgemm_kernel<true><<<grid, 256, HG_SMEM>>>(A, bhi, blo, bias, C, M, N, K, ldc);
    else      hgemm_kernel<false><<<grid, 256, HG_SMEM>>>(A, bhi, blo, bias, C, M, N, K, ldc);
}

static void flash(float* qkv, float* ctx, const int* qtok, const int* ktok, int mode) {
    flash_kernel<<<dim3(kS / 64, kB * kH), 128, FA_SMEM>>>(
        qkv, qkv + kD, qkv + 2 * kD, ctx, qtok, ktok, mode);
}

extern "C" void kernel_launch(void* const* d_in, const int* in_sizes, int n_in,
                              void* d_out, int out_size) {
    const int*   src     = (const int*)d_in[0];
    const int*   tgt     = (const int*)d_in[1];
    const float* enc_emb = (const float*)d_in[2];
    const float* dec_emb = (const float*)d_in[3];
    const float* pos     = (const float*)d_in[4];
    const float* enc_aw  = (const float*)d_in[5];
    const float* enc_ab  = (const float*)d_in[6];
    const float* enc_w1  = (const float*)d_in[7];
    const float* enc_b1  = (const float*)d_in[8];
    const float* enc_w2  = (const float*)d_in[9];
    const float* enc_b2  = (const float*)d_in[10];
    const float* enc_lng = (const float*)d_in[11];
    const float* enc_lnb = (const float*)d_in[12];
    const float* dec_aw  = (const float*)d_in[13];
    const float* dec_ab  = (const float*)d_in[14];
    const float* dec_w1  = (const float*)d_in[15];
    const float* dec_b1  = (const float*)d_in[16];
    const float* dec_w2  = (const float*)d_in[17];
    const float* dec_b2  = (const float*)d_in[18];
    const float* dec_lng = (const float*)d_in[19];
    const float* dec_lnb = (const float*)d_in[20];
    const float* fc_w    = (const float*)d_in[21];
    const float* fc_b    = (const float*)d_in[22];

    float *x, *y, *qkv, *ctx, *t, *ffn;
    __half *whi, *wlo;
    cudaGetSymbolAddress((void**)&x,   g_x);
    cudaGetSymbolAddress((void**)&y,   g_y);
    cudaGetSymbolAddress((void**)&qkv, g_qkv);
    cudaGetSymbolAddress((void**)&ctx, g_ctx);
    cudaGetSymbolAddress((void**)&t,   g_t);
    cudaGetSymbolAddress((void**)&ffn, g_ffn);
    cudaGetSymbolAddress((void**)&whi, g_whi);
    cudaGetSymbolAddress((void**)&wlo, g_wlo);

    cudaFuncSetAttribute(hgemm_kernel<false>, cudaFuncAttributeMaxDynamicSharedMemorySize, HG_SMEM);
    cudaFuncSetAttribute(hgemm_kernel<true>,  cudaFuncAttributeMaxDynamicSharedMemorySize, HG_SMEM);
    cudaFuncSetAttribute(flash_kernel, cudaFuncAttributeMaxDynamicSharedMemorySize, FA_SMEM);

    const int embBlocks = (kNT * kD) / 256;

    // launch order: 5 launches, then the first hgemm (ncu -s 5 profiles it)
    wconv_kernel<<<dim3(16, 16, 24), 256>>>(enc_aw, whi + OFF_EA, wlo + OFF_EA, kD, kD);
    wconv_kernel<<<dim3(64, 16, 6),  256>>>(enc_w1, whi + OFF_EW1, wlo + OFF_EW1, kD, kF);
    wconv_kernel<<<dim3(16, 64, 6),  256>>>(enc_w2, whi + OFF_EW2, wlo + OFF_EW2, kF, kD);
    embed_kernel<<<embBlocks, 256>>>(src, enc_emb, pos, x);
    wconv_kernel<<<dim3(16, 16, 48), 256>>>(dec_aw, whi + OFF_DA, wlo + OFF_DA, kD, kD);

    // ---------------- encoder ----------------
    for (int l = 0; l < kL; l++) {
        const __half* wh = whi + OFF_EA + (size_t)l * 4 * DD;
        const __half* wl = wlo + OFF_EA + (size_t)l * 4 * DD;
        const float* Wb = enc_ab + (size_t)l * 4 * kD;
        hgemm(x, wh, wl, Wb, qkv, kNT, 3 * kD, kD, 3 * kD, false);
        flash(qkv, ctx, nullptr, src, 0);
        hgemm(ctx, wh + 3 * DD, wl + 3 * DD, Wb + 3 * kD, t, kNT, kD, kD, kD, false);
        add_ln_kernel<<<kNT, 128>>>(x, t, enc_lng + (size_t)(l * 2 + 0) * kD,
                                    enc_lnb + (size_t)(l * 2 + 0) * kD);
        hgemm(x, whi + OFF_EW1 + (size_t)l * DF, wlo + OFF_EW1 + (size_t)l * DF,
              enc_b1 + (size_t)l * kF, ffn, kNT, kF, kD, kF, true);
        hgemm(ffn, whi + OFF_EW2 + (size_t)l * DF, wlo + OFF_EW2 + (size_t)l * DF,
              enc_b2 + (size_t)l * kD, t, kNT, kD, kF, kD, false);
        add_ln_kernel<<<kNT, 128>>>(x, t, enc_lng + (size_t)(l * 2 + 1) * kD,
                                    enc_lnb + (size_t)(l * 2 + 1) * kD);
    }

    // remaining conversions + decoder embedding
    wconv_kernel<<<dim3(64, 16, 6), 256>>>(dec_w1, whi + OFF_DW1, wlo + OFF_DW1, kD, kF);
    wconv_kernel<<<dim3(16, 64, 6), 256>>>(dec_w2, whi + OFF_DW2, wlo + OFF_DW2, kF, kD);
    wconv_kernel<<<dim3(1000, 16, 1), 256>>>(fc_w, whi + OFF_FC, wlo + OFF_FC, kD, kV);
    embed_kernel<<<embBlocks, 256>>>(tgt, dec_emb, pos, y);

    // ---------------- decoder ----------------
    for (int l = 0; l < kL; l++) {
        const __half* wh = whi + OFF_DA + (size_t)l * 8 * DD;
        const __half* wl = wlo + OFF_DA + (size_t)l * 8 * DD;
        const float* Wb = dec_ab + (size_t)l * 8 * kD;
        // self-attention (fused QKV, causal + query-validity)
        hgemm(y, wh, wl, Wb, qkv, kNT, 3 * kD, kD, 3 * kD, false);
        flash(qkv, ctx, tgt, tgt, 1);
        hgemm(ctx, wh + 3 * DD, wl + 3 * DD, Wb + 3 * kD, t, kNT, kD, kD, kD, false);
        add_ln_kernel<<<kNT, 128>>>(y, t, dec_lng + (size_t)(l * 3 + 0) * kD,
                                    dec_lnb + (size_t)(l * 3 + 0) * kD);
        // cross-attention: q from y, fused KV from enc_out x
        hgemm(y, wh + 4 * DD, wl + 4 * DD, Wb + 4 * kD, qkv, kNT, kD, kD, 3 * kD, false);
        hgemm(x, wh + 5 * DD, wl + 5 * DD, Wb + 5 * kD, qkv + kD, kNT, 2 * kD, kD, 3 * kD, false);
        flash(qkv, ctx, nullptr, src, 0);
        hgemm(ctx, wh + 7 * DD, wl + 7 * DD, Wb + 7 * kD, t, kNT, kD, kD, kD, false);
        add_ln_kernel<<<kNT, 128>>>(y, t, dec_lng + (size_t)(l * 3 + 1) * kD,
                                    dec_lnb + (size_t)(l * 3 + 1) * kD);
        // FFN
        hgemm(y, whi + OFF_DW1 + (size_t)l * DF, wlo + OFF_DW1 + (size_t)l * DF,
              dec_b1 + (size_t)l * kF, ffn, kNT, kF, kD, kF, true);
        hgemm(ffn, whi + OFF_DW2 + (size_t)l * DF, wlo + OFF_DW2 + (size_t)l * DF,
              dec_b2 + (size_t)l * kD, t, kNT, kD, kF, kD, false);
        add_ln_kernel<<<kNT, 128>>>(y, t, dec_lng + (size_t)(l * 3 + 2) * kD,
                                    dec_lnb + (size_t)(l * 3 + 2) * kD);
    }

    // ---------------- final projection to vocab ----------------
    hgemm(y, whi + OFF_FC, wlo + OFF_FC, fc_b, (float*)d_out, kNT, kV, kD, kV, false);
}

// round 5
// speedup vs baseline: 2.8689x; 1.0562x over previous
#include <cuda_runtime.h>
#include <cuda_fp16.h>
#include <cstddef>
#include <cstdint>

// ---------------- problem constants ----------------
constexpr int kB = 8;
constexpr int kS = 512;
constexpr int kD = 512;
constexpr int kH = 8;
constexpr int kDK = 64;
constexpr int kL = 6;
constexpr int kF = 2048;
constexpr int kV = 32000;
constexpr int kNT = kB * kS;
constexpr float kNEG = -1e9f;
constexpr float kEPS = 1e-5f;
constexpr float kSCALE = 0.125f;

// ---------------- fp16 weight scratch layout (transposed to [N,K]) ---------
constexpr size_t DD  = (size_t)kD * kD;
constexpr size_t DF  = (size_t)kD * kF;
constexpr size_t OFF_EA  = 0;
constexpr size_t OFF_DA  = OFF_EA  + 24 * DD;
constexpr size_t OFF_EW1 = OFF_DA  + 48 * DD;
constexpr size_t OFF_EW2 = OFF_EW1 + 6 * DF;
constexpr size_t OFF_DW1 = OFF_EW2 + 6 * DF;
constexpr size_t OFF_DW2 = OFF_DW1 + 6 * DF;
constexpr size_t OFF_FC  = OFF_DW2 + 6 * DF;
constexpr size_t W_TOTAL = OFF_FC + (size_t)kV * kD;

// ---------------- device scratch ----------------
__device__ float g_x[kNT * kD];
__device__ float g_y[kNT * kD];
__device__ float g_qkv[kNT * 3 * kD];
__device__ float g_ctx[kNT * kD];
__device__ float g_t[kNT * kD];
__device__ float g_ffn[kNT * kF];
__device__ __half g_whi[W_TOTAL];
__device__ __half g_wlo[W_TOTAL];
__device__ __half g_ahi[(size_t)kNT * kF];   // activation hi (max 4096x2048)
__device__ __half g_alo[(size_t)kNT * kF];   // activation lo
__device__ __half g_ehi[kNT * kD];           // enc_out hi (for all cross-KV)
__device__ __half g_elo[kNT * kD];

// ========================= helpers ==========================================
__device__ __forceinline__ uint32_t smem_u32(const void* p) {
    uint32_t a;
    asm("{ .reg .u64 t; cvta.to.shared.u64 t, %1; cvt.u32.u64 %0, t; }"
        : "=r"(a) : "l"(p));
    return a;
}

__device__ __forceinline__ void ldsm_x4(uint32_t (&r)[4], uint32_t addr) {
    asm volatile("ldmatrix.sync.aligned.m8n8.x4.shared.b16 {%0,%1,%2,%3}, [%4];"
                 : "=r"(r[0]), "=r"(r[1]), "=r"(r[2]), "=r"(r[3]) : "r"(addr));
}
__device__ __forceinline__ void ldsm_x4_t(uint32_t (&r)[4], uint32_t addr) {
    asm volatile("ldmatrix.sync.aligned.m8n8.x4.trans.shared.b16 {%0,%1,%2,%3}, [%4];"
                 : "=r"(r[0]), "=r"(r[1]), "=r"(r[2]), "=r"(r[3]) : "r"(addr));
}

__device__ __forceinline__ void mma16816(float (&c)[4], const uint32_t (&a)[4],
                                         const uint32_t* b) {
    asm volatile(
        "mma.sync.aligned.m16n8k16.row.col.f32.f16.f16.f32 "
        "{%0,%1,%2,%3}, {%4,%5,%6,%7}, {%8,%9}, {%0,%1,%2,%3};"
        : "+f"(c[0]), "+f"(c[1]), "+f"(c[2]), "+f"(c[3])
        : "r"(a[0]), "r"(a[1]), "r"(a[2]), "r"(a[3]), "r"(b[0]), "r"(b[1]));
}

__device__ __forceinline__ uint32_t pk_h2(__half a, __half b) {
    __half2 t = __halves2half2(a, b);
    return *reinterpret_cast<uint32_t*>(&t);
}

__device__ __forceinline__ void cp16(uint32_t dst, const void* src) {
    asm volatile("cp.async.cg.shared.global [%0], [%1], 16;" :: "r"(dst), "l"(src));
}
#define CP_COMMIT() asm volatile("cp.async.commit_group;")
template <int N>
__device__ __forceinline__ void cp_wait() {
    asm volatile("cp.async.wait_group %0;" :: "n"(N));
}

// ============== batched weight transpose + fp16 hi/lo split =================
__global__ __launch_bounds__(256)
void wconv_kernel(const float* __restrict__ W, __half* __restrict__ hi,
                  __half* __restrict__ lo, int K, int N) {
    const size_t moff = (size_t)blockIdx.z * K * N;
    W += moff; hi += moff; lo += moff;
    __shared__ float t[32][33];
    const int n0 = blockIdx.x << 5, k0 = blockIdx.y << 5;
    const int tx = threadIdx.x & 31, ty = threadIdx.x >> 5;
#pragma unroll
    for (int j = 0; j < 32; j += 8)
        t[ty + j][tx] = W[(size_t)(k0 + ty + j) * N + n0 + tx];
    __syncthreads();
#pragma unroll
    for (int j = 0; j < 32; j += 8) {
        float v = t[tx][ty + j];
        __half h = __float2half_rn(v);
        __half l = __float2half_rn(v - __half2float(h));
        size_t o = (size_t)(n0 + ty + j) * K + k0 + tx;
        hi[o] = h;
        lo[o] = l;
    }
}

// ============== activation fp32 -> fp16 hi/lo split (row-major) =============
__global__ __launch_bounds__(256)
void aconv_kernel(const float* __restrict__ A, __half* __restrict__ hi,
                  __half* __restrict__ lo) {
    size_t i = ((size_t)blockIdx.x * 256 + threadIdx.x) * 4;
    float4 v = *(const float4*)(A + i);
    __half hx = __float2half_rn(v.x), hy = __float2half_rn(v.y);
    __half hz = __float2half_rn(v.z), hw = __float2half_rn(v.w);
    uint2 h = { pk_h2(hx, hy), pk_h2(hz, hw) };
    uint2 l = { pk_h2(__float2half_rn(v.x - __half2float(hx)),
                      __float2half_rn(v.y - __half2float(hy))),
                pk_h2(__float2half_rn(v.z - __half2float(hz)),
                      __float2half_rn(v.w - __half2float(hw))) };
    *(uint2*)(hi + i) = h;
    *(uint2*)(lo + i) = l;
}

// ======== HMMA GEMM: C = A[M,K](fp16 hi/lo) * Bt[N,K](fp16 hi/lo) + bias ====
// BN=128, BK=32, 256 threads (2x4 warps). BM template: 128 (mt=4) or 64 (mt=2).
// cp.async 2-stage pipeline; 3-pass fp16 hi/lo MMA.
constexpr int APAD = 40;                      // halfs per smem row (80B, 16B-aligned)

template <int BM, bool RELU>
__global__ __launch_bounds__(256, 2)
void hgemm_kernel(const __half* __restrict__ Ahi, const __half* __restrict__ Alo,
                  const __half* __restrict__ Bhi, const __half* __restrict__ Blo,
                  const float* __restrict__ bias, float* __restrict__ C,
                  int M, int N, int K, int ldc) {
    constexpr int MT  = BM / 32;              // 16-row m-tiles per warp
    constexpr int SAB = BM * APAD * 2;        // bytes per A plane
    constexpr int SBB = 128 * APAD * 2;       // bytes per B plane
    constexpr int STG = 2 * (SAB + SBB);      // stage bytes

    extern __shared__ char sm[];
    const int tid = threadIdx.x;
    const int lid = tid & 31, wid = tid >> 5;
    const int wm = wid >> 2, wn = wid & 3;
    const int bm = blockIdx.y * BM, bn = blockIdx.x << 7;
    const uint32_t smb = smem_u32(sm);

    auto ISSUE = [&](int ch) {
        const int s = ch & 1;
        const uint32_t sb = smb + s * STG;
        const int ko = ch * 32;
#pragma unroll
        for (int it = 0; it < BM / 64; it++) {
            int id = tid + (it << 8);
            int r = id >> 2, c8 = (id & 3) << 3;
            uint32_t d = sb + (uint32_t)(r * APAD + c8) * 2;
            size_t g = (size_t)(bm + r) * K + ko + c8;
            cp16(d, Ahi + g);
            cp16(d + SAB, Alo + g);
        }
#pragma unroll
        for (int it = 0; it < 2; it++) {
            int id = tid + (it << 8);
            int r = id >> 2, c8 = (id & 3) << 3;
            uint32_t d = sb + 2 * SAB + (uint32_t)(r * APAD + c8) * 2;
            size_t g = (size_t)(bn + r) * K + ko + c8;
            cp16(d, Bhi + g);
            cp16(d + SBB, Blo + g);
        }
    };

    float acc[MT][4][4] = {};

    const int a_row = (lid & 7) + ((lid >> 3) & 1) * 8;
    const int a_kq = (lid >> 4) * 8;
    const int b_row = wn * 32 + (lid & 7) + (lid >> 4) * 8;
    const int b_kq = ((lid >> 3) & 1) * 8;

    auto COMPUTE = [&](int s) {
        const uint32_t sA = smb + s * STG;
        const uint32_t sB = sA + 2 * SAB;
#pragma unroll
        for (int kk = 0; kk < 2; kk++) {
            uint32_t bh[2][4], bl[2][4];
#pragma unroll
            for (int p = 0; p < 2; p++) {
                uint32_t bd = sB + (uint32_t)(((p * 16 + b_row) * APAD) + kk * 16 + b_kq) * 2;
                ldsm_x4(bh[p], bd);
                ldsm_x4(bl[p], bd + SBB);
            }
#pragma unroll
            for (int mt = 0; mt < MT; mt++) {
                uint32_t ah[4], al[4];
                uint32_t ad = sA + (uint32_t)(((wm * (BM / 2) + mt * 16 + a_row) * APAD)
                                              + kk * 16 + a_kq) * 2;
                ldsm_x4(ah, ad);
                ldsm_x4(al, ad + SAB);
#pragma unroll
                for (int nt = 0; nt < 4; nt++) {
                    const uint32_t* bhf = &bh[nt >> 1][(nt & 1) * 2];
                    const uint32_t* blf = &bl[nt >> 1][(nt & 1) * 2];
                    mma16816(acc[mt][nt], ah, bhf);
                    mma16816(acc[mt][nt], ah, blf);
                    mma16816(acc[mt][nt], al, bhf);
                }
            }
        }
    };

    const int nch = K >> 5;
    ISSUE(0); CP_COMMIT();
    ISSUE(1); CP_COMMIT();
    for (int ch = 0; ch < nch; ch++) {
        cp_wait<1>();
        __syncthreads();
        COMPUTE(ch & 1);
        __syncthreads();
        if (ch + 2 < nch) { ISSUE(ch + 2); CP_COMMIT(); }
    }

    // epilogue: direct float2 stores with bias (+relu)
    const int er = bm + wm * (BM / 2) + (lid >> 2);
    const int ec = bn + wn * 32 + (lid & 3) * 2;
#pragma unroll
    for (int mt = 0; mt < MT; mt++)
#pragma unroll
        for (int nt = 0; nt < 4; nt++) {
            int r0 = er + mt * 16, c0 = ec + nt * 8;
            float2 b2 = *(const float2*)(bias + c0);
            float2 v0 = make_float2(acc[mt][nt][0] + b2.x, acc[mt][nt][1] + b2.y);
            float2 v1 = make_float2(acc[mt][nt][2] + b2.x, acc[mt][nt][3] + b2.y);
            if (RELU) {
                v0.x = fmaxf(v0.x, 0.f); v0.y = fmaxf(v0.y, 0.f);
                v1.x = fmaxf(v1.x, 0.f); v1.y = fmaxf(v1.y, 0.f);
            }
            *(float2*)(C + (size_t)r0 * ldc + c0) = v0;
            *(float2*)(C + (size_t)(r0 + 8) * ldc + c0) = v1;
        }
}

constexpr int HG_SMEM128 = 2 * (2 * (128 * APAD * 2 + 128 * APAD * 2));  // 81920
constexpr int HG_SMEM64  = 2 * (2 * (64 * APAD * 2 + 128 * APAD * 2));   // 61440

// ================= fused flash attention (HMMA fp16 hi/lo 3-pass) ===========
constexpr int FAP = 72;
constexpr int FA_TILE = 64 * FAP;
constexpr int FA_SMEM = 6 * FA_TILE * 2 + 512 * 4;

__global__ __launch_bounds__(128)
void flash_kernel(const float* __restrict__ Qp, const float* __restrict__ Kp,
                  const float* __restrict__ Vp, float* __restrict__ O,
                  const int* __restrict__ qtok, const int* __restrict__ ktok,
                  int mode) {
    extern __shared__ char sm[];
    __half* sQh = (__half*)sm;
    __half* sQl = sQh + FA_TILE;
    __half* sKh = sQl + FA_TILE;
    __half* sKl = sKh + FA_TILE;
    __half* sVh = sKl + FA_TILE;
    __half* sVl = sVh + FA_TILE;
    float* maskf = (float*)(sVl + FA_TILE);

    const int tid = threadIdx.x, lid = tid & 31, w = tid >> 5;
    const int bh = blockIdx.y, b = bh >> 3, h = bh & 7;
    const int q0 = blockIdx.x << 6;
    const uint32_t smb = smem_u32(sm);
    const uint32_t QH_O = 0, QL_O = FA_TILE * 2, KH_O = 2 * FA_TILE * 2,
                   KL_O = 3 * FA_TILE * 2, VH_O = 4 * FA_TILE * 2,
                   VL_O = 5 * FA_TILE * 2;

    if (mode == 0) {
        for (int i = tid; i < kS; i += 128)
            maskf[i] = (ktok[b * kS + i] != 0) ? 1.0f : 0.0f;
    }

    {
        const float* Qb = Qp + (size_t)(b * kS + q0) * 1536 + h * kDK;
#pragma unroll
        for (int it = 0; it < 8; it++) {
            int i = tid + (it << 7);
            int r = i >> 4, c4 = (i & 15) << 2;
            float4 v = *(const float4*)(Qb + (size_t)r * 1536 + c4);
            __half hx = __float2half_rn(v.x), hy = __float2half_rn(v.y);
            __half hz = __float2half_rn(v.z), hw = __float2half_rn(v.w);
            *(uint2*)(sQh + r * FAP + c4) = make_uint2(pk_h2(hx, hy), pk_h2(hz, hw));
            *(uint2*)(sQl + r * FAP + c4) = make_uint2(
                pk_h2(__float2half_rn(v.x - __half2float(hx)),
                      __float2half_rn(v.y - __half2float(hy))),
                pk_h2(__float2half_rn(v.z - __half2float(hz)),
                      __float2half_rn(v.w - __half2float(hw))));
        }
    }

    float m0 = -1e30f, m1 = -1e30f, l0 = 0.f, l1 = 0.f;
    float o[8][4] = {};

    const int qg0 = q0 + w * 16 + (lid >> 2);
    const int qg1 = qg0 + 8;
    bool qv0 = true, qv1 = true;
    if (mode == 1) {
        qv0 = qtok[b * kS + qg0] != 0;
        qv1 = qtok[b * kS + qg1] != 0;
    }
    const int anyinv = __syncthreads_or(mode == 1 && (!qv0 || !qv1));
    const int ktmax = (mode == 1 && !anyinv) ? blockIdx.x : (kS / 64 - 1);

    const int a_row = (lid & 7) + ((lid >> 3) & 1) * 8;
    const int a_kq = (lid >> 4) * 8;
    const int b_row = (lid & 7) + (lid >> 4) * 8;
    const int b_kq = ((lid >> 3) & 1) * 8;
    const int v_row = (lid & 7) + ((lid >> 3) & 1) * 8;
    const int v_col8 = (lid >> 4) * 8;

    for (int kt = 0; kt <= ktmax; kt++) {
        const float* Kb = Kp + (size_t)(b * kS + kt * 64) * 1536 + h * kDK;
        const float* Vb = Vp + (size_t)(b * kS + kt * 64) * 1536 + h * kDK;
#pragma unroll
        for (int it = 0; it < 8; it++) {
            int i = tid + (it << 7);
            int r = i >> 4, c4 = (i & 15) << 2;
            float4 kv = *(const float4*)(Kb + (size_t)r * 1536 + c4);
            float4 vv = *(const float4*)(Vb + (size_t)r * 1536 + c4);
            __half khx = __float2half_rn(kv.x), khy = __float2half_rn(kv.y);
            __half khz = __float2half_rn(kv.z), khw = __float2half_rn(kv.w);
            *(uint2*)(sKh + r * FAP + c4) = make_uint2(pk_h2(khx, khy), pk_h2(khz, khw));
            *(uint2*)(sKl + r * FAP + c4) = make_uint2(
                pk_h2(__float2half_rn(kv.x - __half2float(khx)),
                      __float2half_rn(kv.y - __half2float(khy))),
                pk_h2(__float2half_rn(kv.z - __half2float(khz)),
                      __float2half_rn(kv.w - __half2float(khw))));
            __half vhx = __float2half_rn(vv.x), vhy = __float2half_rn(vv.y);
            __half vhz = __float2half_rn(vv.z), vhw = __float2half_rn(vv.w);
            *(uint2*)(sVh + r * FAP + c4) = make_uint2(pk_h2(vhx, vhy), pk_h2(vhz, vhw));
            *(uint2*)(sVl + r * FAP + c4) = make_uint2(
                pk_h2(__float2half_rn(vv.x - __half2float(vhx)),
                      __float2half_rn(vv.y - __half2float(vhy))),
                pk_h2(__float2half_rn(vv.z - __half2float(vhz)),
                      __float2half_rn(vv.w - __half2float(vhw))));
        }
        __syncthreads();

        float s[8][4] = {};
#pragma unroll
        for (int kk = 0; kk < 4; kk++) {
            uint32_t ah[4], al[4];
            uint32_t ad = smb + QH_O + (uint32_t)(((w * 16 + a_row) * FAP) + kk * 16 + a_kq) * 2;
            ldsm_x4(ah, ad);
            ldsm_x4(al, ad + (QL_O - QH_O));
#pragma unroll
            for (int p = 0; p < 4; p++) {
                uint32_t bhf[4], blf[4];
                uint32_t bd = smb + KH_O + (uint32_t)(((p * 16 + b_row) * FAP) + kk * 16 + b_kq) * 2;
                ldsm_x4(bhf, bd);
                ldsm_x4(blf, bd + (KL_O - KH_O));
#pragma unroll
                for (int t = 0; t < 2; t++) {
                    mma16816(s[p * 2 + t], ah, &bhf[t * 2]);
                    mma16816(s[p * 2 + t], ah, &blf[t * 2]);
                    mma16816(s[p * 2 + t], al, &bhf[t * 2]);
                }
            }
        }

        float mx0 = -1e30f, mx1 = -1e30f;
#pragma unroll
        for (int j = 0; j < 8; j++) {
            int colb = 8 * j + 2 * (lid & 3);
#pragma unroll
            for (int e = 0; e < 4; e++) {
                int kg = kt * 64 + colb + (e & 1);
                float val = s[j][e] * kSCALE;
                if (mode == 0) {
                    val = (maskf[kg] != 0.0f) ? val : kNEG;
                } else {
                    bool qv = (e < 2) ? qv0 : qv1;
                    int qg = (e < 2) ? qg0 : qg1;
                    val = (qv && kg <= qg) ? val : kNEG;
                }
                s[j][e] = val;
                if (e < 2) mx0 = fmaxf(mx0, val);
                else       mx1 = fmaxf(mx1, val);
            }
        }
        mx0 = fmaxf(mx0, __shfl_xor_sync(0xffffffffu, mx0, 1));
        mx0 = fmaxf(mx0, __shfl_xor_sync(0xffffffffu, mx0, 2));
        mx1 = fmaxf(mx1, __shfl_xor_sync(0xffffffffu, mx1, 1));
        mx1 = fmaxf(mx1, __shfl_xor_sync(0xffffffffu, mx1, 2));

        float mn0 = fmaxf(m0, mx0), mn1 = fmaxf(m1, mx1);
        float al0 = __expf(m0 - mn0), al1 = __expf(m1 - mn1);
        m0 = mn0; m1 = mn1;

        float sum0 = 0.f, sum1 = 0.f;
#pragma unroll
        for (int j = 0; j < 8; j++) {
            s[j][0] = __expf(s[j][0] - mn0); sum0 += s[j][0];
            s[j][1] = __expf(s[j][1] - mn0); sum0 += s[j][1];
            s[j][2] = __expf(s[j][2] - mn1); sum1 += s[j][2];
            s[j][3] = __expf(s[j][3] - mn1); sum1 += s[j][3];
        }
        sum0 += __shfl_xor_sync(0xffffffffu, sum0, 1);
        sum0 += __shfl_xor_sync(0xffffffffu, sum0, 2);
        sum1 += __shfl_xor_sync(0xffffffffu, sum1, 1);
        sum1 += __shfl_xor_sync(0xffffffffu, sum1, 2);
        l0 = l0 * al0 + sum0;
        l1 = l1 * al1 + sum1;

#pragma unroll
        for (int j = 0; j < 8; j++) {
            o[j][0] *= al0; o[j][1] *= al0;
            o[j][2] *= al1; o[j][3] *= al1;
        }

#pragma unroll
        for (int kc = 0; kc < 4; kc++) {
            uint32_t ph[4], pl[4];
#pragma unroll
            for (int half16 = 0; half16 < 2; half16++) {
                int j = 2 * kc + half16;
                __half h0 = __float2half_rn(s[j][0]);
                __half h1 = __float2half_rn(s[j][1]);
                __half h2 = __float2half_rn(s[j][2]);
                __half h3 = __float2half_rn(s[j][3]);
                ph[half16 * 2 + 0] = pk_h2(h0, h1);
                ph[half16 * 2 + 1] = pk_h2(h2, h3);
                pl[half16 * 2 + 0] = pk_h2(__float2half_rn(s[j][0] - __half2float(h0)),
                                           __float2half_rn(s[j][1] - __half2float(h1)));
                pl[half16 * 2 + 1] = pk_h2(__float2half_rn(s[j][2] - __half2float(h2)),
                                           __float2half_rn(s[j][3] - __half2float(h3)));
            }
            uint32_t pha[4] = { ph[0], ph[1], ph[2], ph[3] };
            uint32_t pla[4] = { pl[0], pl[1], pl[2], pl[3] };
#pragma unroll
            for (int dp = 0; dp < 4; dp++) {
                uint32_t vh[4], vl[4];
                uint32_t vd = smb + VH_O + (uint32_t)(((kc * 16 + v_row) * FAP) + dp * 16 + v_col8) * 2;
                ldsm_x4_t(vh, vd);
                ldsm_x4_t(vl, vd + (VL_O - VH_O));
#pragma unroll
                for (int t = 0; t < 2; t++) {
                    mma16816(o[dp * 2 + t], pha, &vh[t * 2]);
                    mma16816(o[dp * 2 + t], pha, &vl[t * 2]);
                    mma16816(o[dp * 2 + t], pla, &vh[t * 2]);
                }
            }
        }
        __syncthreads();
    }

    const float inv0 = 1.0f / l0, inv1 = 1.0f / l1;
    float* O0 = O + (size_t)(b * kS + q0 + w * 16 + (lid >> 2)) * kD + h * kDK;
    float* O1 = O0 + 8 * kD;
#pragma unroll
    for (int j = 0; j < 8; j++) {
        int colb = 8 * j + 2 * (lid & 3);
        *(float2*)(O0 + colb) = make_float2(o[j][0] * inv0, o[j][1] * inv0);
        *(float2*)(O1 + colb) = make_float2(o[j][2] * inv1, o[j][3] * inv1);
    }
}

// ---------------- embedding + positional encoding ----------------
__global__ void embed_kernel(const int* __restrict__ tok,
                             const float* __restrict__ emb,
                             const float* __restrict__ pos,
                             float* __restrict__ out) {
    int i = blockIdx.x * blockDim.x + threadIdx.x;
    int d = i & (kD - 1);
    int t = i >> 9;
    int s = t & (kS - 1);
    out[i] = emb[(size_t)tok[t] * kD + d] + pos[s * kD + d];
}

// ---------------- x = LayerNorm(x + a) * g + b ----------------
__global__ __launch_bounds__(128)
void add_ln_kernel(float* __restrict__ x, const float* __restrict__ a,
                   const float* __restrict__ g, const float* __restrict__ bet) {
    const int r = blockIdx.x;
    const int tid = threadIdx.x;
    __shared__ float red[4];

    float v[4];
#pragma unroll
    for (int i = 0; i < 4; i++) {
        int c = tid + (i << 7);
        size_t idx = (size_t)r * kD + c;
        v[i] = x[idx] + a[idx];
    }

    float s = v[0] + v[1] + v[2] + v[3];
    for (int o = 16; o; o >>= 1) s += __shfl_xor_sync(0xffffffffu, s, o);
    if ((tid & 31) == 0) red[tid >> 5] = s;
    __syncthreads();
    s = red[0] + red[1] + red[2] + red[3];
    __syncthreads();
    const float mu = s * (1.0f / kD);

    float sq = 0.0f;
#pragma unroll
    for (int i = 0; i < 4; i++) { float d = v[i] - mu; sq += d * d; }
    for (int o = 16; o; o >>= 1) sq += __shfl_xor_sync(0xffffffffu, sq, o);
    if ((tid & 31) == 0) red[tid >> 5] = sq;
    __syncthreads();
    sq = red[0] + red[1] + red[2] + red[3];
    const float rstd = rsqrtf(sq * (1.0f / kD) + kEPS);

#pragma unroll
    for (int i = 0; i < 4; i++) {
        int c = tid + (i << 7);
        x[(size_t)r * kD + c] = (v[i] - mu) * rstd * g[c] + bet[c];
    }
}

// ---------------- host-side orchestration ----------------------------------
static __half *s_ahi, *s_alo;

static void aconv(const float* A, __half* hi, __half* lo, size_t n) {
    aconv_kernel<<<(unsigned)(n / 1024), 256>>>(A, hi, lo);
}

static void hgemm(const __half* ahi, const __half* alo,
                  const __half* bhi, const __half* blo,
                  const float* bias, float* C, int M, int N, int K, int ldc,
                  bool relu) {
    if (N == 512) {
        dim3 grid(N / 128, M / 64);
        if (relu) hgemm_kernel<64, true><<<grid, 256, HG_SMEM64>>>(ahi, alo, bhi, blo, bias, C, M, N, K, ldc);
        else      hgemm_kernel<64, false><<<grid, 256, HG_SMEM64>>>(ahi, alo, bhi, blo, bias, C, M, N, K, ldc);
    } else {
        dim3 grid(N / 128, M / 128);
        if (relu) hgemm_kernel<128, true><<<grid, 256, HG_SMEM128>>>(ahi, alo, bhi, blo, bias, C, M, N, K, ldc);
        else      hgemm_kernel<128, false><<<grid, 256, HG_SMEM128>>>(ahi, alo, bhi, blo, bias, C, M, N, K, ldc);
    }
}

static void flash(float* qkv, float* ctx, const int* qtok, const int* ktok, int mode) {
    flash_kernel<<<dim3(kS / 64, kB * kH), 128, FA_SMEM>>>(
        qkv, qkv + kD, qkv + 2 * kD, ctx, qtok, ktok, mode);
}

extern "C" void kernel_launch(void* const* d_in, const int* in_sizes, int n_in,
                              void* d_out, int out_size) {
    const int*   src     = (const int*)d_in[0];
    const int*   tgt     = (const int*)d_in[1];
    const float* enc_emb = (const float*)d_in[2];
    const float* dec_emb = (const float*)d_in[3];
    const float* pos     = (const float*)d_in[4];
    const float* enc_aw  = (const float*)d_in[5];
    const float* enc_ab  = (const float*)d_in[6];
    const float* enc_w1  = (const float*)d_in[7];
    const float* enc_b1  = (const float*)d_in[8];
    const float* enc_w2  = (const float*)d_in[9];
    const float* enc_b2  = (const float*)d_in[10];
    const float* enc_lng = (const float*)d_in[11];
    const float* enc_lnb = (const float*)d_in[12];
    const float* dec_aw  = (const float*)d_in[13];
    const float* dec_ab  = (const float*)d_in[14];
    const float* dec_w1  = (const float*)d_in[15];
    const float* dec_b1  = (const float*)d_in[16];
    const float* dec_w2  = (const float*)d_in[17];
    const float* dec_b2  = (const float*)d_in[18];
    const float* dec_lng = (const float*)d_in[19];
    const float* dec_lnb = (const float*)d_in[20];
    const float* fc_w    = (const float*)d_in[21];
    const float* fc_b    = (const float*)d_in[22];

    float *x, *y, *qkv, *ctx, *t, *ffn;
    __half *whi, *wlo, *ahi, *alo, *ehi, *elo;
    cudaGetSymbolAddress((void**)&x,   g_x);
    cudaGetSymbolAddress((void**)&y,   g_y);
    cudaGetSymbolAddress((void**)&qkv, g_qkv);
    cudaGetSymbolAddress((void**)&ctx, g_ctx);
    cudaGetSymbolAddress((void**)&t,   g_t);
    cudaGetSymbolAddress((void**)&ffn, g_ffn);
    cudaGetSymbolAddress((void**)&whi, g_whi);
    cudaGetSymbolAddress((void**)&wlo, g_wlo);
    cudaGetSymbolAddress((void**)&ahi, g_ahi);
    cudaGetSymbolAddress((void**)&alo, g_alo);
    cudaGetSymbolAddress((void**)&ehi, g_ehi);
    cudaGetSymbolAddress((void**)&elo, g_elo);

    cudaFuncSetAttribute(hgemm_kernel<128, false>, cudaFuncAttributeMaxDynamicSharedMemorySize, HG_SMEM128);
    cudaFuncSetAttribute(hgemm_kernel<128, true>,  cudaFuncAttributeMaxDynamicSharedMemorySize, HG_SMEM128);
    cudaFuncSetAttribute(hgemm_kernel<64, false>,  cudaFuncAttributeMaxDynamicSharedMemorySize, HG_SMEM64);
    cudaFuncSetAttribute(hgemm_kernel<64, true>,   cudaFuncAttributeMaxDynamicSharedMemorySize, HG_SMEM64);
    cudaFuncSetAttribute(flash_kernel, cudaFuncAttributeMaxDynamicSharedMemorySize, FA_SMEM);

    const int embBlocks = (kNT * kD) / 256;
    const size_t ND = (size_t)kNT * kD;

    // launches 0-4, then launch 5 = first hgemm (ncu -s 5 profiles it)
    wconv_kernel<<<dim3(16, 16, 24), 256>>>(enc_aw, whi + OFF_EA, wlo + OFF_EA, kD, kD);
    wconv_kernel<<<dim3(64, 16, 6),  256>>>(enc_w1, whi + OFF_EW1, wlo + OFF_EW1, kD, kF);
    wconv_kernel<<<dim3(16, 64, 6),  256>>>(enc_w2, whi + OFF_EW2, wlo + OFF_EW2, kF, kD);
    embed_kernel<<<embBlocks, 256>>>(src, enc_emb, pos, x);
    aconv(x, ahi, alo, ND);

    // ---------------- encoder ----------------
    for (int l = 0; l < kL; l++) {
        const __half* wh = whi + OFF_EA + (size_t)l * 4 * DD;
        const __half* wl = wlo + OFF_EA + (size_t)l * 4 * DD;
        const float* Wb = enc_ab + (size_t)l * 4 * kD;
        if (l > 0) aconv(x, ahi, alo, ND);
        hgemm(ahi, alo, wh, wl, Wb, qkv, kNT, 3 * kD, kD, 3 * kD, false);
        flash(qkv, ctx, nullptr, src, 0);
        aconv(ctx, ahi, alo, ND);
        hgemm(ahi, alo, wh + 3 * DD, wl + 3 * DD, Wb + 3 * kD, t, kNT, kD, kD, kD, false);
        add_ln_kernel<<<kNT, 128>>>(x, t, enc_lng + (size_t)(l * 2 + 0) * kD,
                                    enc_lnb + (size_t)(l * 2 + 0) * kD);
        aconv(x, ahi, alo, ND);
        hgemm(ahi, alo, whi + OFF_EW1 + (size_t)l * DF, wlo + OFF_EW1 + (size_t)l * DF,
              enc_b1 + (size_t)l * kF, ffn, kNT, kF, kD, kF, true);
        aconv(ffn, ahi, alo, (size_t)kNT * kF);
        hgemm(ahi, alo, whi + OFF_EW2 + (size_t)l * DF, wlo + OFF_EW2 + (size_t)l * DF,
              enc_b2 + (size_t)l * kD, t, kNT, kD, kF, kD, false);
        add_ln_kernel<<<kNT, 128>>>(x, t, enc_lng + (size_t)(l * 2 + 1) * kD,
                                    enc_lnb + (size_t)(l * 2 + 1) * kD);
    }

    // enc_out fp16 (used by all 6 cross-attentions) + remaining conversions
    aconv(x, ehi, elo, ND);
    wconv_kernel<<<dim3(16, 16, 48), 256>>>(dec_aw, whi + OFF_DA, wlo + OFF_DA, kD, kD);
    wconv_kernel<<<dim3(64, 16, 6), 256>>>(dec_w1, whi + OFF_DW1, wlo + OFF_DW1, kD, kF);
    wconv_kernel<<<dim3(16, 64, 6), 256>>>(dec_w2, whi + OFF_DW2, wlo + OFF_DW2, kF, kD);
    wconv_kernel<<<dim3(1000, 16, 1), 256>>>(fc_w, whi + OFF_FC, wlo + OFF_FC, kD, kV);
    embed_kernel<<<embBlocks, 256>>>(tgt, dec_emb, pos, y);

    // ---------------- decoder ----------------
    for (int l = 0; l < kL; l++) {
        const __half* wh = whi + OFF_DA + (size_t)l * 8 * DD;
        const __half* wl = wlo + OFF_DA + (size_t)l * 8 * DD;
        const float* Wb = dec_ab + (size_t)l * 8 * kD;
        // self-attention (fused QKV, causal + query-validity)
        aconv(y, ahi, alo, ND);
        hgemm(ahi, alo, wh, wl, Wb, qkv, kNT, 3 * kD, kD, 3 * kD, false);
        flash(qkv, ctx, tgt, tgt, 1);
        aconv(ctx, ahi, alo, ND);
        hgemm(ahi, alo, wh + 3 * DD, wl + 3 * DD, Wb + 3 * kD, t, kNT, kD, kD, kD, false);
        add_ln_kernel<<<kNT, 128>>>(y, t, dec_lng + (size_t)(l * 3 + 0) * kD,
                                    dec_lnb + (size_t)(l * 3 + 0) * kD);
        // cross-attention: q from y, fused KV from enc_out
        aconv(y, ahi, alo, ND);
        hgemm(ahi, alo, wh + 4 * DD, wl + 4 * DD, Wb + 4 * kD, qkv, kNT, kD, kD, 3 * kD, false);
        hgemm(ehi, elo, wh + 5 * DD, wl + 5 * DD, Wb + 5 * kD, qkv + kD, kNT, 2 * kD, kD, 3 * kD, false);
        flash(qkv, ctx, nullptr, src, 0);
        aconv(ctx, ahi, alo, ND);
        hgemm(ahi, alo, wh + 7 * DD, wl + 7 * DD, Wb + 7 * kD, t, kNT, kD, kD, kD, false);
        add_ln_kernel<<<kNT, 128>>>(y, t, dec_lng + (size_t)(l * 3 + 1) * kD,
                                    dec_lnb + (size_t)(l * 3 + 1) * kD);
        // FFN
        aconv(y, ahi, alo, ND);
        hgemm(ahi, alo, whi + OFF_DW1 + (size_t)l * DF, wlo + OFF_DW1 + (size_t)l * DF,
              dec_b1 + (size_t)l * kF, ffn, kNT, kF, kD, kF, true);
        aconv(ffn, ahi, alo, (size_t)kNT * kF);
        hgemm(ahi, alo, whi + OFF_DW2 + (size_t)l * DF, wlo + OFF_DW2 + (size_t)l * DF,
              dec_b2 + (size_t)l * kD, t, kNT, kD, kF, kD, false);
        add_ln_kernel<<<kNT, 128>>>(y, t, dec_lng + (size_t)(l * 3 + 2) * kD,
                                    dec_lnb + (size_t)(l * 3 + 2) * kD);
    }

    // ---------------- final projection to vocab ----------------
    aconv(y, ahi, alo, ND);
    hgemm(ahi, alo, whi + OFF_FC, wlo + OFF_FC, fc_b, (float*)d_out, kNT, kV, kD, kV, false);
}